// round 2
// baseline (speedup 1.0000x reference)
#include <cuda_runtime.h>
#include <cstdint>

#define NND 16384
#define NE  262144
#define HID 128
#define BATCH 128
#define SEQ 128
#define NL 4

// ---------------- scratch (device globals; no allocs allowed) ----------------
__device__ float g_h[NND * HID];
__device__ float g_e[NE * HID];
__device__ float g_eij[NE * HID];          // Ce, then e_ij in-place
__device__ float g_Ax[NND * HID];          // also q
__device__ float g_Bx[NND * HID];          // also k
__device__ float g_Dx[NND * HID];          // also v
__device__ float g_Ex[NND * HID];          // also attn out o
__device__ float g_num[NND * HID];
__device__ float g_den[NND * HID];
__device__ float g_part[2048 * HID * 2];
__device__ float g_scN[HID], g_shN[HID], g_scE[HID], g_shE[HID];
__device__ float g_pool[BATCH * HID];
__device__ float g_t1[BATCH * 64];
__device__ float g_t2[BATCH * 32];

// ---------------- input projection: h = [x@node_w+b, pe@pe_w+b] ----------------
__global__ void input_proj_kernel(const float* __restrict__ x, const float* __restrict__ pe,
                                  const float* __restrict__ nw, const float* __restrict__ nb,
                                  const float* __restrict__ pw, const float* __restrict__ pb) {
    int row = blockIdx.x;
    int c = threadIdx.x;
    __shared__ float xs[64];
    __shared__ float ps[16];
    if (c < 64) xs[c] = x[row * 64 + c];
    else if (c < 80) ps[c - 64] = pe[row * 16 + (c - 64)];
    __syncthreads();
    float acc;
    if (c < 112) {
        acc = nb[c];
#pragma unroll
        for (int k = 0; k < 64; k++) acc += xs[k] * nw[k * 112 + c];
    } else {
        int cc = c - 112;
        acc = pb[cc];
#pragma unroll
        for (int k = 0; k < 16; k++) acc += ps[k] * pw[k * 16 + cc];
    }
    g_h[row * HID + c] = acc;
}

// ---------------- generic C[M,128] = A[M,128] @ W[128,128] + bias ----------------
__global__ __launch_bounds__(256) void gemm128_kernel(const float* __restrict__ A,
                                                      const float* __restrict__ W,
                                                      const float* __restrict__ bias,
                                                      float* __restrict__ C) {
    __shared__ float As[16][132];   // transposed A tile, padded
    __shared__ float Ws[16][128];
    int tid = threadIdx.x;
    int tx = tid & 15, ty = tid >> 4;
    int r0 = blockIdx.x * 128;
    float acc[8][8];
#pragma unroll
    for (int m = 0; m < 8; m++)
#pragma unroll
        for (int n = 0; n < 8; n++) acc[m][n] = 0.f;

    for (int k0 = 0; k0 < 128; k0 += 16) {
#pragma unroll
        for (int i = 0; i < 2; i++) {
            int idx = tid + i * 256;
            int r = idx >> 2, q = idx & 3;
            float4 a = *(const float4*)&A[(r0 + r) * HID + k0 + q * 4];
            As[q * 4 + 0][r] = a.x; As[q * 4 + 1][r] = a.y;
            As[q * 4 + 2][r] = a.z; As[q * 4 + 3][r] = a.w;
        }
#pragma unroll
        for (int i = 0; i < 2; i++) {
            int idx = tid + i * 256;
            int rr = idx >> 5, c4 = idx & 31;
            *(float4*)&Ws[rr][c4 * 4] = *(const float4*)&W[(k0 + rr) * HID + c4 * 4];
        }
        __syncthreads();
#pragma unroll 4
        for (int kk = 0; kk < 16; kk++) {
            float aR[8], bR[8];
            *(float4*)&aR[0] = *(float4*)&As[kk][ty * 8];
            *(float4*)&aR[4] = *(float4*)&As[kk][ty * 8 + 4];
            *(float4*)&bR[0] = *(float4*)&Ws[kk][tx * 8];
            *(float4*)&bR[4] = *(float4*)&Ws[kk][tx * 8 + 4];
#pragma unroll
            for (int m = 0; m < 8; m++)
#pragma unroll
                for (int n = 0; n < 8; n++) acc[m][n] += aR[m] * bR[n];
        }
        __syncthreads();
    }
    float bR[8];
    *(float4*)&bR[0] = *(const float4*)&bias[tx * 8];
    *(float4*)&bR[4] = *(const float4*)&bias[tx * 8 + 4];
#pragma unroll
    for (int m = 0; m < 8; m++) {
        int row = r0 + ty * 8 + m;
        float4 o0 = make_float4(acc[m][0] + bR[0], acc[m][1] + bR[1],
                                acc[m][2] + bR[2], acc[m][3] + bR[3]);
        float4 o1 = make_float4(acc[m][4] + bR[4], acc[m][5] + bR[5],
                                acc[m][6] + bR[6], acc[m][7] + bR[7]);
        *(float4*)&C[row * HID + tx * 8] = o0;
        *(float4*)&C[row * HID + tx * 8 + 4] = o1;
    }
}

// ---------------- zero num/den ----------------
__global__ void zero_nd_kernel() {
    int i = blockIdx.x * blockDim.x + threadIdx.x;
    if (i < NND * HID) { g_num[i] = 0.f; g_den[i] = 0.f; }
}

// ---------------- edge: e_ij = Dx[dst]+Ex[src]+Ce; scatter sigma, sigma*Bx[src] ----------------
__global__ void edge_kernel(const float* __restrict__ Dx, const float* __restrict__ Ex,
                            const float* __restrict__ Bx, const int* __restrict__ src,
                            const int* __restrict__ dst, float* __restrict__ eij) {
    int t = threadIdx.x;
    int e0 = blockIdx.x * 8;
#pragma unroll 1
    for (int j = 0; j < 8; j++) {
        int k = e0 + j;
        int s = src[k], d = dst[k];
        float v = Dx[d * HID + t] + Ex[s * HID + t] + eij[k * HID + t];
        eij[k * HID + t] = v;
        float sg = 1.f / (1.f + __expf(-v));
        atomicAdd(&g_num[d * HID + t], sg * Bx[s * HID + t]);
        atomicAdd(&g_den[d * HID + t], sg);
    }
}

// ---------------- BN stats (partial sums per block, thread==channel) ----------------
__global__ void bn_stats_kernel(const float* __restrict__ v, int M) {
    int c = threadIdx.x;
    float s = 0.f, ss = 0.f;
    for (int r = blockIdx.x; r < M; r += gridDim.x) {
        float x = v[r * HID + c];
        s += x; ss += x * x;
    }
    g_part[(blockIdx.x * HID + c) * 2] = s;
    g_part[(blockIdx.x * HID + c) * 2 + 1] = ss;
}

// ---------------- h_new = Ax + num/(den+eps), fused with BN stats ----------------
__global__ void node_hnew_stats_kernel() {
    int c = threadIdx.x;
    float s = 0.f, ss = 0.f;
    for (int r = blockIdx.x; r < NND; r += gridDim.x) {
        int i = r * HID + c;
        float v = g_Ax[i] + g_num[i] / (g_den[i] + 1e-6f);
        g_Ax[i] = v;
        s += v; ss += v * v;
    }
    g_part[(blockIdx.x * HID + c) * 2] = s;
    g_part[(blockIdx.x * HID + c) * 2 + 1] = ss;
}

// ---------------- BN finalize (double accumulation for accuracy) ----------------
__global__ void bn_finalize_kernel(int G, float invM, const float* __restrict__ gamma,
                                   const float* __restrict__ beta,
                                   float* __restrict__ scale, float* __restrict__ shift) {
    int c = threadIdx.x;
    double s = 0.0, ss = 0.0;
    for (int g = 0; g < G; g++) {
        s  += (double)g_part[(g * HID + c) * 2];
        ss += (double)g_part[(g * HID + c) * 2 + 1];
    }
    double mu = s * (double)invM;
    double var = ss * (double)invM - mu * mu;
    float inv = rsqrtf((float)var + 1e-5f);
    float sc = gamma[c] * inv;
    scale[c] = sc;
    shift[c] = beta[c] - (float)mu * sc;
}

// ---------------- BN apply + relu + residual (vectorized) ----------------
__global__ void bn_apply_kernel(const float* __restrict__ v, const float* __restrict__ scale,
                                const float* __restrict__ shift, const float* __restrict__ resid,
                                float* __restrict__ out, int n4) {
    int i = blockIdx.x * blockDim.x + threadIdx.x;
    if (i >= n4) return;
    int c4 = i & 31;
    float4 vv = ((const float4*)v)[i];
    float4 rr = ((const float4*)resid)[i];
    float4 sc = ((const float4*)scale)[c4];
    float4 sh = ((const float4*)shift)[c4];
    float4 o;
    o.x = fmaxf(vv.x * sc.x + sh.x, 0.f) + rr.x;
    o.y = fmaxf(vv.y * sc.y + sh.y, 0.f) + rr.y;
    o.z = fmaxf(vv.z * sc.z + sh.z, 0.f) + rr.z;
    o.w = fmaxf(vv.w * sc.w + sh.w, 0.f) + rr.w;
    ((float4*)out)[i] = o;
}

// ---------------- dense attention per (head, batch graph) ----------------
__global__ void attn_kernel(const float* __restrict__ q, const float* __restrict__ k,
                            const float* __restrict__ v, const float* __restrict__ sph,
                            float* __restrict__ o) {
    extern __shared__ float sm[];
    float* ks = sm;                 // [128][36]
    float* vs = sm + 128 * 36;      // [128][36]
    float* ps = sm + 2 * 128 * 36;  // [128][133]
    int head = blockIdx.x, b = blockIdx.y;
    int s = threadIdx.x;
    int nodebase = (b * SEQ + s) * HID + head * 32;
    float qr[32];
#pragma unroll
    for (int d4 = 0; d4 < 8; d4++) {
        float4 tq = *(const float4*)&q[nodebase + d4 * 4];
        qr[d4 * 4] = tq.x; qr[d4 * 4 + 1] = tq.y; qr[d4 * 4 + 2] = tq.z; qr[d4 * 4 + 3] = tq.w;
        *(float4*)&ks[s * 36 + d4 * 4] = *(const float4*)&k[nodebase + d4 * 4];
        *(float4*)&vs[s * 36 + d4 * 4] = *(const float4*)&v[nodebase + d4 * 4];
    }
    __syncthreads();
    const float isd = 0.17677669529663687f;  // 1/sqrt(32)
    for (int t = 0; t < SEQ; t++) {
        float acc = 0.f;
#pragma unroll
        for (int d4 = 0; d4 < 8; d4++) {
            float4 kk = *(float4*)&ks[t * 36 + d4 * 4];
            acc += qr[d4 * 4] * kk.x + qr[d4 * 4 + 1] * kk.y +
                   qr[d4 * 4 + 2] * kk.z + qr[d4 * 4 + 3] * kk.w;
        }
        ps[s * 133 + t] = acc * isd;
    }
    __syncthreads();
    // multiply sph with coalesced global reads
    const float* sb = sph + b * SEQ * SEQ;
    for (int i = s; i < SEQ * SEQ; i += 128) {
        int s2 = i >> 7, t2 = i & 127;
        ps[s2 * 133 + t2] *= sb[i];
    }
    __syncthreads();
    // softmax over own row
    float mx = -1e30f;
    for (int t = 0; t < SEQ; t++) mx = fmaxf(mx, ps[s * 133 + t]);
    float sum = 0.f;
    for (int t = 0; t < SEQ; t++) {
        float e = __expf(ps[s * 133 + t] - mx);
        ps[s * 133 + t] = e;
        sum += e;
    }
    float inv = 1.f / sum;
    float acc[32];
#pragma unroll
    for (int d = 0; d < 32; d++) acc[d] = 0.f;
    for (int t = 0; t < SEQ; t++) {
        float p = ps[s * 133 + t] * inv;
#pragma unroll
        for (int d4 = 0; d4 < 8; d4++) {
            float4 vvv = *(float4*)&vs[t * 36 + d4 * 4];
            acc[d4 * 4] += p * vvv.x; acc[d4 * 4 + 1] += p * vvv.y;
            acc[d4 * 4 + 2] += p * vvv.z; acc[d4 * 4 + 3] += p * vvv.w;
        }
    }
#pragma unroll
    for (int d4 = 0; d4 < 8; d4++) {
        float4 t4 = make_float4(acc[d4 * 4], acc[d4 * 4 + 1], acc[d4 * 4 + 2], acc[d4 * 4 + 3]);
        *(float4*)&o[nodebase + d4 * 4] = t4;
    }
}

// ---------------- mean pool per graph ----------------
__global__ void pool_kernel() {
    int b = blockIdx.x, c = threadIdx.x;
    float s = 0.f;
    for (int i = 0; i < SEQ; i++) s += g_h[(b * SEQ + i) * HID + c];
    g_pool[b * HID + c] = s * (1.f / 128.f);
}

// ---------------- tiny MLP layer ----------------
__global__ void mlp_kernel(const float* __restrict__ in, const float* __restrict__ W,
                           const float* __restrict__ bias, float* __restrict__ out,
                           int K, int Ncol, int doRelu) {
    int r = blockIdx.x;
    __shared__ float xs[128];
    if ((int)threadIdx.x < K) xs[threadIdx.x] = in[r * K + threadIdx.x];
    __syncthreads();
    int c = threadIdx.x;
    if (c < Ncol) {
        float acc = bias[c];
        for (int k = 0; k < K; k++) acc += xs[k] * W[k * Ncol + c];
        if (doRelu) acc = fmaxf(acc, 0.f);
        out[r * Ncol + c] = acc;
    }
}

// ---------------- launch ----------------
extern "C" void kernel_launch(void* const* d_in, const int* in_sizes, int n_in,
                              void* d_out, int out_size) {
    const float* x        = (const float*)d_in[0];
    const float* pe       = (const float*)d_in[1];
    const float* edge_attr= (const float*)d_in[2];
    const float* sph      = (const float*)d_in[3];
    const float* node_w   = (const float*)d_in[4];
    const float* node_b   = (const float*)d_in[5];
    const float* pe_w     = (const float*)d_in[6];
    const float* pe_b     = (const float*)d_in[7];
    const float* Aw       = (const float*)d_in[8];
    const float* Ab       = (const float*)d_in[9];
    const float* Bw       = (const float*)d_in[10];
    const float* Bb       = (const float*)d_in[11];
    const float* Cw       = (const float*)d_in[12];
    const float* Cb       = (const float*)d_in[13];
    const float* Dw       = (const float*)d_in[14];
    const float* Db       = (const float*)d_in[15];
    const float* Ew       = (const float*)d_in[16];
    const float* Eb       = (const float*)d_in[17];
    const float* bnxg     = (const float*)d_in[18];
    const float* bnxb     = (const float*)d_in[19];
    const float* bneg     = (const float*)d_in[20];
    const float* bneb     = (const float*)d_in[21];
    const float* attw     = (const float*)d_in[22];
    const float* attb     = (const float*)d_in[23];
    const float* m1w      = (const float*)d_in[24];
    const float* m1b      = (const float*)d_in[25];
    const float* m2w      = (const float*)d_in[26];
    const float* m2b      = (const float*)d_in[27];
    const float* m3w      = (const float*)d_in[28];
    const float* m3b      = (const float*)d_in[29];
    const int*   ei       = (const int*)d_in[30];
    float* out = (float*)d_out;

    float *p_h, *p_e, *p_eij, *p_Ax, *p_Bx, *p_Dx, *p_Ex;
    float *p_scN, *p_shN, *p_scE, *p_shE, *p_pool, *p_t1, *p_t2;
    cudaGetSymbolAddress((void**)&p_h,   g_h);
    cudaGetSymbolAddress((void**)&p_e,   g_e);
    cudaGetSymbolAddress((void**)&p_eij, g_eij);
    cudaGetSymbolAddress((void**)&p_Ax,  g_Ax);
    cudaGetSymbolAddress((void**)&p_Bx,  g_Bx);
    cudaGetSymbolAddress((void**)&p_Dx,  g_Dx);
    cudaGetSymbolAddress((void**)&p_Ex,  g_Ex);
    cudaGetSymbolAddress((void**)&p_scN, g_scN);
    cudaGetSymbolAddress((void**)&p_shN, g_shN);
    cudaGetSymbolAddress((void**)&p_scE, g_scE);
    cudaGetSymbolAddress((void**)&p_shE, g_shE);
    cudaGetSymbolAddress((void**)&p_pool,g_pool);
    cudaGetSymbolAddress((void**)&p_t1,  g_t1);
    cudaGetSymbolAddress((void**)&p_t2,  g_t2);

    const int* src = ei;
    const int* dst = ei + NE;
    const int ATTN_SMEM = (2 * 128 * 36 + 128 * 133) * 4;  // 104960 B
    cudaFuncSetAttribute(attn_kernel, cudaFuncAttributeMaxDynamicSharedMemorySize, ATTN_SMEM);

    input_proj_kernel<<<NND, 128>>>(x, pe, node_w, node_b, pe_w, pe_b);

    const float* e_in = edge_attr;
    const int WS = HID * HID;
    for (int l = 0; l < NL; l++) {
        gemm128_kernel<<<NND / 128, 256>>>(p_h, Aw + l * WS, Ab + l * HID, p_Ax);
        gemm128_kernel<<<NND / 128, 256>>>(p_h, Bw + l * WS, Bb + l * HID, p_Bx);
        gemm128_kernel<<<NND / 128, 256>>>(p_h, Dw + l * WS, Db + l * HID, p_Dx);
        gemm128_kernel<<<NND / 128, 256>>>(p_h, Ew + l * WS, Eb + l * HID, p_Ex);
        gemm128_kernel<<<NE / 128, 256>>>(e_in, Cw + l * WS, Cb + l * HID, p_eij);
        zero_nd_kernel<<<(NND * HID) / 256, 256>>>();
        edge_kernel<<<NE / 8, 128>>>(p_Dx, p_Ex, p_Bx, src, dst, p_eij);
        bn_stats_kernel<<<2048, 128>>>(p_eij, NE);
        bn_finalize_kernel<<<1, 128>>>(2048, 1.f / NE, bneg + l * HID, bneb + l * HID, p_scE, p_shE);
        node_hnew_stats_kernel<<<256, 128>>>();
        bn_finalize_kernel<<<1, 128>>>(256, 1.f / NND, bnxg + l * HID, bnxb + l * HID, p_scN, p_shN);
        bn_apply_kernel<<<(NE * 32) / 256, 256>>>(p_eij, p_scE, p_shE, e_in, p_e, NE * 32);
        bn_apply_kernel<<<(NND * 32) / 256, 256>>>(p_Ax, p_scN, p_shN, p_h, p_h, NND * 32);
        // attention
        gemm128_kernel<<<NND / 128, 256>>>(p_h, attw + 0 * WS, attb + 0 * HID, p_Ax);
        gemm128_kernel<<<NND / 128, 256>>>(p_h, attw + 1 * WS, attb + 1 * HID, p_Bx);
        gemm128_kernel<<<NND / 128, 256>>>(p_h, attw + 2 * WS, attb + 2 * HID, p_Dx);
        dim3 ag(4, BATCH);
        attn_kernel<<<ag, 128, ATTN_SMEM>>>(p_Ax, p_Bx, p_Dx, sph, p_Ex);
        gemm128_kernel<<<NND / 128, 256>>>(p_Ex, attw + 3 * WS, attb + 3 * HID, p_h);
        e_in = p_e;
    }
    pool_kernel<<<BATCH, 128>>>();
    mlp_kernel<<<BATCH, 128>>>(p_pool, m1w, m1b, p_t1, 128, 64, 1);
    mlp_kernel<<<BATCH, 128>>>(p_t1, m2w, m2b, p_t2, 64, 32, 1);
    mlp_kernel<<<BATCH, 128>>>(p_t2, m3w, m3b, out, 32, 10, 0);
}

// round 3
// speedup vs baseline: 1.9517x; 1.9517x over previous
#include <cuda_runtime.h>
#include <cstdint>

#define NND 16384
#define NE  262144
#define HID 128
#define BATCH 128
#define SEQ 128
#define NL 4
#define WSZ (HID*HID)

// ---------------- scratch ----------------
__device__ float g_h[NND * HID];
__device__ float g_e[NE * HID];
__device__ float g_eij[NE * HID];
__device__ float g_Ax[NND * HID];
__device__ float g_Bx[NND * HID];
__device__ float g_Dx[NND * HID];
__device__ float g_Ex[NND * HID];
__device__ float g_num[NND * HID];
__device__ float g_den[NND * HID];
__device__ float g_part[2048 * HID * 2];
__device__ float g_scN[HID], g_shN[HID], g_scE[HID], g_shE[HID];
__device__ float g_pool[BATCH * HID];
__device__ float g_t1[BATCH * 64];
__device__ float g_t2[BATCH * 32];

__device__ __forceinline__ unsigned f2tf(float f) {
    unsigned u; asm("cvt.rna.tf32.f32 %0, %1;" : "=r"(u) : "f"(f)); return u;
}
__device__ __forceinline__ void mma8(float* d, const unsigned* a, const unsigned* b) {
    asm volatile("mma.sync.aligned.m16n8k8.row.col.f32.tf32.tf32.f32 "
        "{%0,%1,%2,%3}, {%4,%5,%6,%7}, {%8,%9}, {%0,%1,%2,%3};"
        : "+f"(d[0]), "+f"(d[1]), "+f"(d[2]), "+f"(d[3])
        : "r"(a[0]), "r"(a[1]), "r"(a[2]), "r"(a[3]), "r"(b[0]), "r"(b[1]));
}

// ---------------- input projection ----------------
__global__ void input_proj_kernel(const float* __restrict__ x, const float* __restrict__ pe,
                                  const float* __restrict__ nw, const float* __restrict__ nb,
                                  const float* __restrict__ pw, const float* __restrict__ pb) {
    int row = blockIdx.x;
    int c = threadIdx.x;
    __shared__ float xs[64];
    __shared__ float ps[16];
    if (c < 64) xs[c] = x[row * 64 + c];
    else if (c < 80) ps[c - 64] = pe[row * 16 + (c - 64)];
    __syncthreads();
    float acc;
    if (c < 112) {
        acc = nb[c];
#pragma unroll
        for (int k = 0; k < 64; k++) acc += xs[k] * nw[k * 112 + c];
    } else {
        int cc = c - 112;
        acc = pb[cc];
#pragma unroll
        for (int k = 0; k < 16; k++) acc += ps[k] * pw[k * 16 + cc];
    }
    g_h[row * HID + c] = acc;
}

// ---------------- tf32 tensor-core GEMM: plain, multi-weight via blockIdx.y ----------------
__global__ __launch_bounds__(256, 2) void gemm_tc_plain(
    const float* __restrict__ A,
    const float* __restrict__ W0, const float* __restrict__ W1,
    const float* __restrict__ W2, const float* __restrict__ W3,
    const float* __restrict__ b0, const float* __restrict__ b1,
    const float* __restrict__ b2, const float* __restrict__ b3,
    float* __restrict__ C0, float* __restrict__ C1,
    float* __restrict__ C2, float* __restrict__ C3) {
    int y = blockIdx.y;
    const float* W = (y == 0) ? W0 : (y == 1) ? W1 : (y == 2) ? W2 : W3;
    const float* bb = (y == 0) ? b0 : (y == 1) ? b1 : (y == 2) ? b2 : b3;
    float* C = (y == 0) ? C0 : (y == 1) ? C1 : (y == 2) ? C2 : C3;

    __shared__ unsigned As[32 * 136];
    __shared__ unsigned Wsm[32 * 136];
    int tid = threadIdx.x, lane = tid & 31, wid = tid >> 5;
    int wm = wid & 3, wn = wid >> 2, g = lane >> 2, t = lane & 3;
    int r0 = blockIdx.x * 128;

    float acc[2][8][4];
#pragma unroll
    for (int i = 0; i < 2; i++)
#pragma unroll
        for (int j = 0; j < 8; j++)
#pragma unroll
            for (int q = 0; q < 4; q++) acc[i][j][q] = 0.f;

    int arow = tid >> 1, acb = (tid & 1) * 16;
    int wrow = tid >> 3, wcb = (tid & 7) * 16;

    for (int k0 = 0; k0 < 128; k0 += 32) {
#pragma unroll
        for (int q = 0; q < 4; q++) {
            int kc = acb + q * 4;
            float4 av = *(const float4*)&A[(r0 + arow) * HID + k0 + kc];
            As[(kc + 0) * 136 + arow] = f2tf(av.x);
            As[(kc + 1) * 136 + arow] = f2tf(av.y);
            As[(kc + 2) * 136 + arow] = f2tf(av.z);
            As[(kc + 3) * 136 + arow] = f2tf(av.w);
            float4 wv = *(const float4*)&W[(k0 + wrow) * HID + wcb + q * 4];
            unsigned* wp = &Wsm[wrow * 136 + wcb + q * 4];
            wp[0] = f2tf(wv.x); wp[1] = f2tf(wv.y); wp[2] = f2tf(wv.z); wp[3] = f2tf(wv.w);
        }
        __syncthreads();
#pragma unroll
        for (int kk = 0; kk < 32; kk += 8) {
            unsigned af[2][4], bf[8][2];
            int ka = (kk + t) * 136, kb = (kk + t + 4) * 136;
#pragma unroll
            for (int mt = 0; mt < 2; mt++) {
                int rb = wm * 32 + mt * 16 + g;
                af[mt][0] = As[ka + rb]; af[mt][1] = As[ka + rb + 8];
                af[mt][2] = As[kb + rb]; af[mt][3] = As[kb + rb + 8];
            }
#pragma unroll
            for (int nt = 0; nt < 8; nt++) {
                int cb = wn * 64 + nt * 8 + g;
                bf[nt][0] = Wsm[ka + cb]; bf[nt][1] = Wsm[kb + cb];
            }
#pragma unroll
            for (int mt = 0; mt < 2; mt++)
#pragma unroll
                for (int nt = 0; nt < 8; nt++)
                    mma8(acc[mt][nt], af[mt], bf[nt]);
        }
        __syncthreads();
    }
#pragma unroll
    for (int mt = 0; mt < 2; mt++) {
#pragma unroll
        for (int nt = 0; nt < 8; nt++) {
            int c = wn * 64 + nt * 8 + 2 * t;
            float bx = bb[c], by = bb[c + 1];
            int r = r0 + wm * 32 + mt * 16 + g;
            *(float2*)&C[r * HID + c] = make_float2(acc[mt][nt][0] + bx, acc[mt][nt][1] + by);
            *(float2*)&C[(r + 8) * HID + c] = make_float2(acc[mt][nt][2] + bx, acc[mt][nt][3] + by);
        }
    }
}

// ---------------- edge GEMM: BN-fold loader + gather/sigmoid/atomic/stats epilogue ----------------
__global__ __launch_bounds__(256, 2) void gemm_tc_edge(
    const float* A,                  // eij_prev (l>0) or edge_attr (l==0); may alias C
    const float* __restrict__ foldE, // residual in (null => no fold)
    float* __restrict__ foldOut,     // residual out (e buffer)
    const float* __restrict__ W, const float* __restrict__ bias,
    float* C,                        // eij out
    const float* __restrict__ Dx, const float* __restrict__ Ex, const float* __restrict__ Bx,
    const int* __restrict__ srcI, const int* __restrict__ dstI, int doStats) {
    extern __shared__ unsigned sm[];
    unsigned* As = sm;
    unsigned* Wsm = sm + 32 * 136;
    float* tile = (float*)sm;            // 128 x 132 overlay after mainloop
    int* sidx = (int*)(sm + 16896);
    int* didx = sidx + 128;
    float* sred = (float*)(didx + 128);  // 512 floats

    int tid = threadIdx.x, lane = tid & 31, wid = tid >> 5;
    int wm = wid & 3, wn = wid >> 2, g = lane >> 2, t = lane & 3;
    int r0 = blockIdx.x * 128;

    if (tid < 128) { sidx[tid] = srcI[r0 + tid]; didx[tid] = dstI[r0 + tid]; }

    float acc[2][8][4];
#pragma unroll
    for (int i = 0; i < 2; i++)
#pragma unroll
        for (int j = 0; j < 8; j++)
#pragma unroll
            for (int q = 0; q < 4; q++) acc[i][j][q] = 0.f;

    int arow = tid >> 1, acb = (tid & 1) * 16;
    int wrow = tid >> 3, wcb = (tid & 7) * 16;
    bool fold = (foldE != nullptr);

    for (int k0 = 0; k0 < 128; k0 += 32) {
#pragma unroll
        for (int q = 0; q < 4; q++) {
            int kc = acb + q * 4;
            float4 av = *(const float4*)&A[(r0 + arow) * HID + k0 + kc];
            if (fold) {
                float4 ev = *(const float4*)&foldE[(r0 + arow) * HID + k0 + kc];
                float4 sc = *(const float4*)&g_scE[k0 + kc];
                float4 sh = *(const float4*)&g_shE[k0 + kc];
                av.x = fmaxf(av.x * sc.x + sh.x, 0.f) + ev.x;
                av.y = fmaxf(av.y * sc.y + sh.y, 0.f) + ev.y;
                av.z = fmaxf(av.z * sc.z + sh.z, 0.f) + ev.z;
                av.w = fmaxf(av.w * sc.w + sh.w, 0.f) + ev.w;
                *(float4*)&foldOut[(r0 + arow) * HID + k0 + kc] = av;
            }
            As[(kc + 0) * 136 + arow] = f2tf(av.x);
            As[(kc + 1) * 136 + arow] = f2tf(av.y);
            As[(kc + 2) * 136 + arow] = f2tf(av.z);
            As[(kc + 3) * 136 + arow] = f2tf(av.w);
            float4 wv = *(const float4*)&W[(k0 + wrow) * HID + wcb + q * 4];
            unsigned* wp = &Wsm[wrow * 136 + wcb + q * 4];
            wp[0] = f2tf(wv.x); wp[1] = f2tf(wv.y); wp[2] = f2tf(wv.z); wp[3] = f2tf(wv.w);
        }
        __syncthreads();
#pragma unroll
        for (int kk = 0; kk < 32; kk += 8) {
            unsigned af[2][4], bf[8][2];
            int ka = (kk + t) * 136, kb = (kk + t + 4) * 136;
#pragma unroll
            for (int mt = 0; mt < 2; mt++) {
                int rb = wm * 32 + mt * 16 + g;
                af[mt][0] = As[ka + rb]; af[mt][1] = As[ka + rb + 8];
                af[mt][2] = As[kb + rb]; af[mt][3] = As[kb + rb + 8];
            }
#pragma unroll
            for (int nt = 0; nt < 8; nt++) {
                int cb = wn * 64 + nt * 8 + g;
                bf[nt][0] = Wsm[ka + cb]; bf[nt][1] = Wsm[kb + cb];
            }
#pragma unroll
            for (int mt = 0; mt < 2; mt++)
#pragma unroll
                for (int nt = 0; nt < 8; nt++)
                    mma8(acc[mt][nt], af[mt], bf[nt]);
        }
        __syncthreads();
    }
    // stage accumulators to smem tile
#pragma unroll
    for (int mt = 0; mt < 2; mt++) {
#pragma unroll
        for (int nt = 0; nt < 8; nt++) {
            int c = wn * 64 + nt * 8 + 2 * t;
            int r = wm * 32 + mt * 16 + g;
            tile[r * 132 + c] = acc[mt][nt][0];
            tile[r * 132 + c + 1] = acc[mt][nt][1];
            tile[(r + 8) * 132 + c] = acc[mt][nt][2];
            tile[(r + 8) * 132 + c + 1] = acc[mt][nt][3];
        }
    }
    __syncthreads();
    // channel-per-thread epilogue: gather + sigmoid + atomics + stats
    int c = tid & 127, half = tid >> 7;
    float bc = bias[c];
    float s1 = 0.f, s2 = 0.f;
#pragma unroll 2
    for (int rr = 0; rr < 64; rr++) {
        int r = half * 64 + rr;
        int d = didx[r], s = sidx[r];
        float v = tile[r * 132 + c] + bc + Dx[d * HID + c] + Ex[s * HID + c];
        C[(r0 + r) * HID + c] = v;
        float sg = 1.f / (1.f + __expf(-v));
        atomicAdd(&g_num[d * HID + c], sg * Bx[s * HID + c]);
        atomicAdd(&g_den[d * HID + c], sg);
        s1 += v; s2 += v * v;
    }
    if (doStats) {
        sred[tid] = s1; sred[256 + tid] = s2;
        __syncthreads();
        if (tid < 128) {
            g_part[(blockIdx.x * HID + tid) * 2] = sred[tid] + sred[tid + 128];
            g_part[(blockIdx.x * HID + tid) * 2 + 1] = sred[256 + tid] + sred[256 + tid + 128];
        }
    }
}

// ---------------- zero num/den ----------------
__global__ void zero_nd_kernel() {
    int i = blockIdx.x * blockDim.x + threadIdx.x;
    ((float4*)g_num)[i] = make_float4(0.f, 0.f, 0.f, 0.f);
    ((float4*)g_den)[i] = make_float4(0.f, 0.f, 0.f, 0.f);
}

// ---------------- h_new = Ax + num/(den+eps) fused with BN partials ----------------
__global__ void node_hnew_stats_kernel() {
    int c = threadIdx.x;
    float s = 0.f, ss = 0.f;
    for (int r = blockIdx.x; r < NND; r += gridDim.x) {
        int i = r * HID + c;
        float v = g_Ax[i] + g_num[i] / (g_den[i] + 1e-6f);
        g_Ax[i] = v;
        s += v; ss += v * v;
    }
    g_part[(blockIdx.x * HID + c) * 2] = s;
    g_part[(blockIdx.x * HID + c) * 2 + 1] = ss;
}

// ---------------- BN finalize: parallel tree, one block per channel ----------------
__global__ void bn_finalize2(int G, float invM, const float* __restrict__ gamma,
                             const float* __restrict__ beta,
                             float* __restrict__ scale, float* __restrict__ shift) {
    int c = blockIdx.x;
    int tid = threadIdx.x;
    double s = 0.0, ss = 0.0;
    for (int gi = tid; gi < G; gi += 256) {
        s  += (double)g_part[(gi * HID + c) * 2];
        ss += (double)g_part[(gi * HID + c) * 2 + 1];
    }
    __shared__ double rs[256], rss[256];
    rs[tid] = s; rss[tid] = ss;
    __syncthreads();
    for (int o = 128; o > 0; o >>= 1) {
        if (tid < o) { rs[tid] += rs[tid + o]; rss[tid] += rss[tid + o]; }
        __syncthreads();
    }
    if (tid == 0) {
        double mu = rs[0] * (double)invM;
        double var = rss[0] * (double)invM - mu * mu;
        float inv = rsqrtf((float)var + 1e-5f);
        float scv = gamma[c] * inv;
        scale[c] = scv;
        shift[c] = beta[c] - (float)mu * scv;
    }
}

// ---------------- BN apply + relu + residual (nodes) ----------------
__global__ void bn_apply_kernel(const float* __restrict__ v, const float* __restrict__ scale,
                                const float* __restrict__ shift, const float* __restrict__ resid,
                                float* __restrict__ out, int n4) {
    int i = blockIdx.x * blockDim.x + threadIdx.x;
    if (i >= n4) return;
    int c4 = i & 31;
    float4 vv = ((const float4*)v)[i];
    float4 rr = ((const float4*)resid)[i];
    float4 sc = ((const float4*)scale)[c4];
    float4 sh = ((const float4*)shift)[c4];
    float4 o;
    o.x = fmaxf(vv.x * sc.x + sh.x, 0.f) + rr.x;
    o.y = fmaxf(vv.y * sc.y + sh.y, 0.f) + rr.y;
    o.z = fmaxf(vv.z * sc.z + sh.z, 0.f) + rr.z;
    o.w = fmaxf(vv.w * sc.w + sh.w, 0.f) + rr.w;
    ((float4*)out)[i] = o;
}

// ---------------- dense attention per (head, batch graph) ----------------
__global__ void attn_kernel(const float* __restrict__ q, const float* __restrict__ k,
                            const float* __restrict__ v, const float* __restrict__ sph,
                            float* __restrict__ o) {
    extern __shared__ float smf[];
    float* ks = smf;
    float* vs = smf + 128 * 36;
    float* ps = smf + 2 * 128 * 36;
    int head = blockIdx.x, b = blockIdx.y;
    int s = threadIdx.x;
    int nodebase = (b * SEQ + s) * HID + head * 32;
    float qr[32];
#pragma unroll
    for (int d4 = 0; d4 < 8; d4++) {
        float4 tq = *(const float4*)&q[nodebase + d4 * 4];
        qr[d4 * 4] = tq.x; qr[d4 * 4 + 1] = tq.y; qr[d4 * 4 + 2] = tq.z; qr[d4 * 4 + 3] = tq.w;
        *(float4*)&ks[s * 36 + d4 * 4] = *(const float4*)&k[nodebase + d4 * 4];
        *(float4*)&vs[s * 36 + d4 * 4] = *(const float4*)&v[nodebase + d4 * 4];
    }
    __syncthreads();
    const float isd = 0.17677669529663687f;
    for (int t = 0; t < SEQ; t++) {
        float acc = 0.f;
#pragma unroll
        for (int d4 = 0; d4 < 8; d4++) {
            float4 kk = *(float4*)&ks[t * 36 + d4 * 4];
            acc += qr[d4 * 4] * kk.x + qr[d4 * 4 + 1] * kk.y +
                   qr[d4 * 4 + 2] * kk.z + qr[d4 * 4 + 3] * kk.w;
        }
        ps[s * 133 + t] = acc * isd;
    }
    __syncthreads();
    const float* sb = sph + b * SEQ * SEQ;
    for (int i = s; i < SEQ * SEQ; i += 128) {
        int s2 = i >> 7, t2 = i & 127;
        ps[s2 * 133 + t2] *= sb[i];
    }
    __syncthreads();
    float mx = -1e30f;
    for (int t = 0; t < SEQ; t++) mx = fmaxf(mx, ps[s * 133 + t]);
    float sum = 0.f;
    for (int t = 0; t < SEQ; t++) {
        float e = __expf(ps[s * 133 + t] - mx);
        ps[s * 133 + t] = e;
        sum += e;
    }
    float inv = 1.f / sum;
    float acc[32];
#pragma unroll
    for (int d = 0; d < 32; d++) acc[d] = 0.f;
    for (int t = 0; t < SEQ; t++) {
        float p = ps[s * 133 + t] * inv;
#pragma unroll
        for (int d4 = 0; d4 < 8; d4++) {
            float4 vvv = *(float4*)&vs[t * 36 + d4 * 4];
            acc[d4 * 4] += p * vvv.x; acc[d4 * 4 + 1] += p * vvv.y;
            acc[d4 * 4 + 2] += p * vvv.z; acc[d4 * 4 + 3] += p * vvv.w;
        }
    }
#pragma unroll
    for (int d4 = 0; d4 < 8; d4++) {
        float4 t4 = make_float4(acc[d4 * 4], acc[d4 * 4 + 1], acc[d4 * 4 + 2], acc[d4 * 4 + 3]);
        *(float4*)&o[nodebase + d4 * 4] = t4;
    }
}

// ---------------- mean pool + tiny MLP ----------------
__global__ void pool_kernel() {
    int b = blockIdx.x, c = threadIdx.x;
    float s = 0.f;
    for (int i = 0; i < SEQ; i++) s += g_h[(b * SEQ + i) * HID + c];
    g_pool[b * HID + c] = s * (1.f / 128.f);
}
__global__ void mlp_kernel(const float* __restrict__ in, const float* __restrict__ W,
                           const float* __restrict__ bias, float* __restrict__ out,
                           int K, int Ncol, int doRelu) {
    int r = blockIdx.x;
    __shared__ float xs[128];
    if ((int)threadIdx.x < K) xs[threadIdx.x] = in[r * K + threadIdx.x];
    __syncthreads();
    int c = threadIdx.x;
    if (c < Ncol) {
        float acc = bias[c];
        for (int k = 0; k < K; k++) acc += xs[k] * W[k * Ncol + c];
        if (doRelu) acc = fmaxf(acc, 0.f);
        out[r * Ncol + c] = acc;
    }
}

// ---------------- launch ----------------
extern "C" void kernel_launch(void* const* d_in, const int* in_sizes, int n_in,
                              void* d_out, int out_size) {
    const float* x        = (const float*)d_in[0];
    const float* pe       = (const float*)d_in[1];
    const float* edge_attr= (const float*)d_in[2];
    const float* sph      = (const float*)d_in[3];
    const float* node_w   = (const float*)d_in[4];
    const float* node_b   = (const float*)d_in[5];
    const float* pe_w     = (const float*)d_in[6];
    const float* pe_b     = (const float*)d_in[7];
    const float* Aw       = (const float*)d_in[8];
    const float* Ab       = (const float*)d_in[9];
    const float* Bw       = (const float*)d_in[10];
    const float* Bb       = (const float*)d_in[11];
    const float* Cw       = (const float*)d_in[12];
    const float* Cb       = (const float*)d_in[13];
    const float* Dw       = (const float*)d_in[14];
    const float* Db       = (const float*)d_in[15];
    const float* Ew       = (const float*)d_in[16];
    const float* Eb       = (const float*)d_in[17];
    const float* bnxg     = (const float*)d_in[18];
    const float* bnxb     = (const float*)d_in[19];
    const float* bneg     = (const float*)d_in[20];
    const float* bneb     = (const float*)d_in[21];
    const float* attw     = (const float*)d_in[22];
    const float* attb     = (const float*)d_in[23];
    const float* m1w      = (const float*)d_in[24];
    const float* m1b      = (const float*)d_in[25];
    const float* m2w      = (const float*)d_in[26];
    const float* m2b      = (const float*)d_in[27];
    const float* m3w      = (const float*)d_in[28];
    const float* m3b      = (const float*)d_in[29];
    const int*   ei       = (const int*)d_in[30];
    float* out = (float*)d_out;

    float *p_h, *p_e, *p_eij, *p_Ax, *p_Bx, *p_Dx, *p_Ex;
    float *p_scN, *p_shN, *p_scE, *p_shE, *p_pool, *p_t1, *p_t2;
    cudaGetSymbolAddress((void**)&p_h,   g_h);
    cudaGetSymbolAddress((void**)&p_e,   g_e);
    cudaGetSymbolAddress((void**)&p_eij, g_eij);
    cudaGetSymbolAddress((void**)&p_Ax,  g_Ax);
    cudaGetSymbolAddress((void**)&p_Bx,  g_Bx);
    cudaGetSymbolAddress((void**)&p_Dx,  g_Dx);
    cudaGetSymbolAddress((void**)&p_Ex,  g_Ex);
    cudaGetSymbolAddress((void**)&p_scN, g_scN);
    cudaGetSymbolAddress((void**)&p_shN, g_shN);
    cudaGetSymbolAddress((void**)&p_scE, g_scE);
    cudaGetSymbolAddress((void**)&p_shE, g_shE);
    cudaGetSymbolAddress((void**)&p_pool,g_pool);
    cudaGetSymbolAddress((void**)&p_t1,  g_t1);
    cudaGetSymbolAddress((void**)&p_t2,  g_t2);

    const int* src = ei;
    const int* dst = ei + NE;
    const int ATTN_SMEM = (2 * 128 * 36 + 128 * 133) * 4;
    const int EDGE_SMEM = (16896 + 256 + 512) * 4;  // 70656
    cudaFuncSetAttribute(attn_kernel, cudaFuncAttributeMaxDynamicSharedMemorySize, ATTN_SMEM);
    cudaFuncSetAttribute(gemm_tc_edge, cudaFuncAttributeMaxDynamicSharedMemorySize, EDGE_SMEM);

    input_proj_kernel<<<NND, 128>>>(x, pe, node_w, node_b, pe_w, pe_b);

    for (int l = 0; l < NL; l++) {
        zero_nd_kernel<<<NND * HID / 4 / 256, 256>>>();
        // A,B,D,E projections in one launch
        dim3 g4(NND / 128, 4);
        gemm_tc_plain<<<g4, 256>>>(p_h,
            Aw + l * WSZ, Bw + l * WSZ, Dw + l * WSZ, Ew + l * WSZ,
            Ab + l * HID, Bb + l * HID, Db + l * HID, Eb + l * HID,
            p_Ax, p_Bx, p_Dx, p_Ex);
        // edge GEMM with fused BN-fold loader + gather/sigmoid/atomic/stats epilogue
        const float* eA    = (l == 0) ? edge_attr : p_eij;
        const float* foldE = (l == 0) ? nullptr : ((l == 1) ? edge_attr : p_e);
        gemm_tc_edge<<<NE / 128, 256, EDGE_SMEM>>>(
            eA, foldE, p_e, Cw + l * WSZ, Cb + l * HID, p_eij,
            p_Dx, p_Ex, p_Bx, src, dst, (l < 3) ? 1 : 0);
        if (l < 3)
            bn_finalize2<<<HID, 256>>>(2048, 1.f / NE, bneg + l * HID, bneb + l * HID, p_scE, p_shE);
        node_hnew_stats_kernel<<<256, 128>>>();
        bn_finalize2<<<HID, 256>>>(256, 1.f / NND, bnxg + l * HID, bnxb + l * HID, p_scN, p_shN);
        bn_apply_kernel<<<(NND * 32) / 256, 256>>>(p_Ax, p_scN, p_shN, p_h, p_h, NND * 32);
        // attention q,k,v in one launch
        dim3 g3(NND / 128, 3);
        gemm_tc_plain<<<g3, 256>>>(p_h,
            attw + 0 * WSZ, attw + 1 * WSZ, attw + 2 * WSZ, attw + 2 * WSZ,
            attb + 0 * HID, attb + 1 * HID, attb + 2 * HID, attb + 2 * HID,
            p_Ax, p_Bx, p_Dx, p_Dx);
        dim3 ag(4, BATCH);
        attn_kernel<<<ag, 128, ATTN_SMEM>>>(p_Ax, p_Bx, p_Dx, sph, p_Ex);
        dim3 g1(NND / 128, 1);
        gemm_tc_plain<<<g1, 256>>>(p_Ex,
            attw + 3 * WSZ, attw + 3 * WSZ, attw + 3 * WSZ, attw + 3 * WSZ,
            attb + 3 * HID, attb + 3 * HID, attb + 3 * HID, attb + 3 * HID,
            p_h, p_h, p_h, p_h);
    }
    pool_kernel<<<BATCH, 128>>>();
    mlp_kernel<<<BATCH, 128>>>(p_pool, m1w, m1b, p_t1, 128, 64, 1);
    mlp_kernel<<<BATCH, 128>>>(p_t1, m2w, m2b, p_t2, 64, 32, 1);
    mlp_kernel<<<BATCH, 128>>>(p_t2, m3w, m3b, out, 32, 10, 0);
}

// round 4
// speedup vs baseline: 2.0714x; 1.0613x over previous
#include <cuda_runtime.h>
#include <cstdint>

#define NND 16384
#define NE  262144
#define HID 128
#define BATCH 128
#define SEQ 128
#define NL 4
#define WSZ (HID*HID)

// ---------------- scratch ----------------
__device__ float g_h[NND * HID];
__device__ float g_e[NE * HID];
__device__ float g_eij[NE * HID];
__device__ float g_Ax[NND * HID];
__device__ float g_Bx[NND * HID];
__device__ float g_Dx[NND * HID];
__device__ float g_Ex[NND * HID];
__device__ float g_num[NND * HID];
__device__ float g_den[NND * HID];
__device__ float g_part[2048 * HID * 2];
__device__ float g_scN[HID], g_shN[HID], g_scE[HID], g_shE[HID];
__device__ float g_pool[BATCH * HID];
__device__ float g_t1[BATCH * 64];
__device__ float g_t2[BATCH * 32];

__device__ __forceinline__ unsigned f2tf(float f) {
    unsigned u; asm("cvt.rna.tf32.f32 %0, %1;" : "=r"(u) : "f"(f)); return u;
}
__device__ __forceinline__ void tfsplit(float f, unsigned& hi, unsigned& lo) {
    hi = f2tf(f);
    lo = f2tf(f - __uint_as_float(hi));
}
__device__ __forceinline__ void mma8(float* d, const unsigned* a, const unsigned* b) {
    asm volatile("mma.sync.aligned.m16n8k8.row.col.f32.tf32.tf32.f32 "
        "{%0,%1,%2,%3}, {%4,%5,%6,%7}, {%8,%9}, {%0,%1,%2,%3};"
        : "+f"(d[0]), "+f"(d[1]), "+f"(d[2]), "+f"(d[3])
        : "r"(a[0]), "r"(a[1]), "r"(a[2]), "r"(a[3]), "r"(b[0]), "r"(b[1]));
}
__device__ __forceinline__ void red4(float* p, float4 v) {
    asm volatile("red.global.add.v4.f32 [%0], {%1,%2,%3,%4};"
        :: "l"(p), "f"(v.x), "f"(v.y), "f"(v.z), "f"(v.w) : "memory");
}

// ---------------- input projection ----------------
__global__ void input_proj_kernel(const float* __restrict__ x, const float* __restrict__ pe,
                                  const float* __restrict__ nw, const float* __restrict__ nb,
                                  const float* __restrict__ pw, const float* __restrict__ pb) {
    int row = blockIdx.x;
    int c = threadIdx.x;
    __shared__ float xs[64];
    __shared__ float ps[16];
    if (c < 64) xs[c] = x[row * 64 + c];
    else if (c < 80) ps[c - 64] = pe[row * 16 + (c - 64)];
    __syncthreads();
    float acc;
    if (c < 112) {
        acc = nb[c];
#pragma unroll
        for (int k = 0; k < 64; k++) acc += xs[k] * nw[k * 112 + c];
    } else {
        int cc = c - 112;
        acc = pb[cc];
#pragma unroll
        for (int k = 0; k < 16; k++) acc += ps[k] * pw[k * 16 + cc];
    }
    g_h[row * HID + c] = acc;
}

// ================= 3xTF32 tensor-core GEMM: plain, multi-weight via blockIdx.y =================
__global__ __launch_bounds__(256, 2) void gemm_tc_plain(
    const float* __restrict__ A,
    const float* __restrict__ W0, const float* __restrict__ W1,
    const float* __restrict__ W2, const float* __restrict__ W3,
    const float* __restrict__ b0, const float* __restrict__ b1,
    const float* __restrict__ b2, const float* __restrict__ b3,
    float* __restrict__ C0, float* __restrict__ C1,
    float* __restrict__ C2, float* __restrict__ C3) {
    int y = blockIdx.y;
    const float* W = (y == 0) ? W0 : (y == 1) ? W1 : (y == 2) ? W2 : W3;
    const float* bb = (y == 0) ? b0 : (y == 1) ? b1 : (y == 2) ? b2 : b3;
    float* C = (y == 0) ? C0 : (y == 1) ? C1 : (y == 2) ? C2 : C3;

    extern __shared__ unsigned sm[];
    unsigned* AsH = sm;
    unsigned* AsL = sm + 4352;
    unsigned* WsH = sm + 8704;
    unsigned* WsL = sm + 13056;

    int tid = threadIdx.x, lane = tid & 31, wid = tid >> 5;
    int wm = wid & 3, wn = wid >> 2, g = lane >> 2, t = lane & 3;
    int r0 = blockIdx.x * 128;

    float acc[2][8][4];
#pragma unroll
    for (int i = 0; i < 2; i++)
#pragma unroll
        for (int j = 0; j < 8; j++)
#pragma unroll
            for (int q = 0; q < 4; q++) acc[i][j][q] = 0.f;

    int arow = tid >> 1, acb = (tid & 1) * 16;
    int wrow = tid >> 3, wcb = (tid & 7) * 16;

    for (int k0 = 0; k0 < 128; k0 += 32) {
#pragma unroll
        for (int q = 0; q < 4; q++) {
            int kc = acb + q * 4;
            float4 av = *(const float4*)&A[(r0 + arow) * HID + k0 + kc];
            unsigned h, l;
            tfsplit(av.x, h, l); AsH[(kc + 0) * 136 + arow] = h; AsL[(kc + 0) * 136 + arow] = l;
            tfsplit(av.y, h, l); AsH[(kc + 1) * 136 + arow] = h; AsL[(kc + 1) * 136 + arow] = l;
            tfsplit(av.z, h, l); AsH[(kc + 2) * 136 + arow] = h; AsL[(kc + 2) * 136 + arow] = l;
            tfsplit(av.w, h, l); AsH[(kc + 3) * 136 + arow] = h; AsL[(kc + 3) * 136 + arow] = l;
            float4 wv = *(const float4*)&W[(k0 + wrow) * HID + wcb + q * 4];
            int wp = wrow * 136 + wcb + q * 4;
            tfsplit(wv.x, h, l); WsH[wp + 0] = h; WsL[wp + 0] = l;
            tfsplit(wv.y, h, l); WsH[wp + 1] = h; WsL[wp + 1] = l;
            tfsplit(wv.z, h, l); WsH[wp + 2] = h; WsL[wp + 2] = l;
            tfsplit(wv.w, h, l); WsH[wp + 3] = h; WsL[wp + 3] = l;
        }
        __syncthreads();
#pragma unroll
        for (int kk = 0; kk < 32; kk += 8) {
            int ka = (kk + t) * 136, kb = (kk + t + 4) * 136;
            unsigned ah[2][4], al[2][4];
#pragma unroll
            for (int mt = 0; mt < 2; mt++) {
                int rb = wm * 32 + mt * 16 + g;
                ah[mt][0] = AsH[ka + rb]; ah[mt][1] = AsH[ka + rb + 8];
                ah[mt][2] = AsH[kb + rb]; ah[mt][3] = AsH[kb + rb + 8];
                al[mt][0] = AsL[ka + rb]; al[mt][1] = AsL[ka + rb + 8];
                al[mt][2] = AsL[kb + rb]; al[mt][3] = AsL[kb + rb + 8];
            }
#pragma unroll
            for (int nt = 0; nt < 8; nt++) {
                int cb = wn * 64 + nt * 8 + g;
                unsigned bh[2] = { WsH[ka + cb], WsH[kb + cb] };
                unsigned bl[2] = { WsL[ka + cb], WsL[kb + cb] };
#pragma unroll
                for (int mt = 0; mt < 2; mt++) {
                    mma8(acc[mt][nt], ah[mt], bh);
                    mma8(acc[mt][nt], al[mt], bh);
                    mma8(acc[mt][nt], ah[mt], bl);
                }
            }
        }
        __syncthreads();
    }
#pragma unroll
    for (int mt = 0; mt < 2; mt++) {
#pragma unroll
        for (int nt = 0; nt < 8; nt++) {
            int c = wn * 64 + nt * 8 + 2 * t;
            float bx = bb[c], by = bb[c + 1];
            int r = r0 + wm * 32 + mt * 16 + g;
            *(float2*)&C[r * HID + c] = make_float2(acc[mt][nt][0] + bx, acc[mt][nt][1] + by);
            *(float2*)&C[(r + 8) * HID + c] = make_float2(acc[mt][nt][2] + bx, acc[mt][nt][3] + by);
        }
    }
}

// ================= edge GEMM: BN-fold loader + gather/sigmoid/red.v4/stats epilogue =================
__global__ __launch_bounds__(256, 2) void gemm_tc_edge(
    const float* A, const float* __restrict__ foldE, float* __restrict__ foldOut,
    const float* __restrict__ W, const float* __restrict__ bias,
    float* C,
    const float* __restrict__ Dx, const float* __restrict__ Ex, const float* __restrict__ Bx,
    const int* __restrict__ srcI, const int* __restrict__ dstI, int doStats) {
    extern __shared__ unsigned sm[];
    unsigned* AsH = sm;
    unsigned* AsL = sm + 4352;
    unsigned* WsH = sm + 8704;
    unsigned* WsL = sm + 13056;           // operand region ends at 17408
    float* tile = (float*)sm;             // overlay 128x132 after mainloop
    int* sidx = (int*)(sm + 17408);
    int* didx = sidx + 128;
    float* sred = (float*)(didx + 128);   // 2048 floats

    int tid = threadIdx.x, lane = tid & 31, wid = tid >> 5;
    int wm = wid & 3, wn = wid >> 2, g = lane >> 2, t = lane & 3;
    int r0 = blockIdx.x * 128;

    if (tid < 128) { sidx[tid] = srcI[r0 + tid]; didx[tid] = dstI[r0 + tid]; }

    float acc[2][8][4];
#pragma unroll
    for (int i = 0; i < 2; i++)
#pragma unroll
        for (int j = 0; j < 8; j++)
#pragma unroll
            for (int q = 0; q < 4; q++) acc[i][j][q] = 0.f;

    int arow = tid >> 1, acb = (tid & 1) * 16;
    int wrow = tid >> 3, wcb = (tid & 7) * 16;
    bool fold = (foldE != nullptr);

    for (int k0 = 0; k0 < 128; k0 += 32) {
#pragma unroll
        for (int q = 0; q < 4; q++) {
            int kc = acb + q * 4;
            float4 av = *(const float4*)&A[(r0 + arow) * HID + k0 + kc];
            if (fold) {
                float4 ev = *(const float4*)&foldE[(r0 + arow) * HID + k0 + kc];
                float4 sc = *(const float4*)&g_scE[k0 + kc];
                float4 sh = *(const float4*)&g_shE[k0 + kc];
                av.x = fmaxf(av.x * sc.x + sh.x, 0.f) + ev.x;
                av.y = fmaxf(av.y * sc.y + sh.y, 0.f) + ev.y;
                av.z = fmaxf(av.z * sc.z + sh.z, 0.f) + ev.z;
                av.w = fmaxf(av.w * sc.w + sh.w, 0.f) + ev.w;
                *(float4*)&foldOut[(r0 + arow) * HID + k0 + kc] = av;
            }
            unsigned h, l;
            tfsplit(av.x, h, l); AsH[(kc + 0) * 136 + arow] = h; AsL[(kc + 0) * 136 + arow] = l;
            tfsplit(av.y, h, l); AsH[(kc + 1) * 136 + arow] = h; AsL[(kc + 1) * 136 + arow] = l;
            tfsplit(av.z, h, l); AsH[(kc + 2) * 136 + arow] = h; AsL[(kc + 2) * 136 + arow] = l;
            tfsplit(av.w, h, l); AsH[(kc + 3) * 136 + arow] = h; AsL[(kc + 3) * 136 + arow] = l;
            float4 wv = *(const float4*)&W[(k0 + wrow) * HID + wcb + q * 4];
            int wp = wrow * 136 + wcb + q * 4;
            tfsplit(wv.x, h, l); WsH[wp + 0] = h; WsL[wp + 0] = l;
            tfsplit(wv.y, h, l); WsH[wp + 1] = h; WsL[wp + 1] = l;
            tfsplit(wv.z, h, l); WsH[wp + 2] = h; WsL[wp + 2] = l;
            tfsplit(wv.w, h, l); WsH[wp + 3] = h; WsL[wp + 3] = l;
        }
        __syncthreads();
#pragma unroll
        for (int kk = 0; kk < 32; kk += 8) {
            int ka = (kk + t) * 136, kb = (kk + t + 4) * 136;
            unsigned ah[2][4], al[2][4];
#pragma unroll
            for (int mt = 0; mt < 2; mt++) {
                int rb = wm * 32 + mt * 16 + g;
                ah[mt][0] = AsH[ka + rb]; ah[mt][1] = AsH[ka + rb + 8];
                ah[mt][2] = AsH[kb + rb]; ah[mt][3] = AsH[kb + rb + 8];
                al[mt][0] = AsL[ka + rb]; al[mt][1] = AsL[ka + rb + 8];
                al[mt][2] = AsL[kb + rb]; al[mt][3] = AsL[kb + rb + 8];
            }
#pragma unroll
            for (int nt = 0; nt < 8; nt++) {
                int cb = wn * 64 + nt * 8 + g;
                unsigned bh[2] = { WsH[ka + cb], WsH[kb + cb] };
                unsigned bl[2] = { WsL[ka + cb], WsL[kb + cb] };
#pragma unroll
                for (int mt = 0; mt < 2; mt++) {
                    mma8(acc[mt][nt], ah[mt], bh);
                    mma8(acc[mt][nt], al[mt], bh);
                    mma8(acc[mt][nt], ah[mt], bl);
                }
            }
        }
        __syncthreads();
    }
    // stage accumulators to smem tile
#pragma unroll
    for (int mt = 0; mt < 2; mt++) {
#pragma unroll
        for (int nt = 0; nt < 8; nt++) {
            int c = wn * 64 + nt * 8 + 2 * t;
            int r = wm * 32 + mt * 16 + g;
            tile[r * 132 + c] = acc[mt][nt][0];
            tile[r * 132 + c + 1] = acc[mt][nt][1];
            tile[(r + 8) * 132 + c] = acc[mt][nt][2];
            tile[(r + 8) * 132 + c + 1] = acc[mt][nt][3];
        }
    }
    __syncthreads();
    // epilogue: 4 channels/thread, vectorized gathers + red.v4 atomics
    int tq = tid & 31, rg = tid >> 5;
    int c4 = tq * 4;
    float4 bcv = *(const float4*)&bias[c4];
    float4 s1v = make_float4(0.f, 0.f, 0.f, 0.f);
    float4 s2v = make_float4(0.f, 0.f, 0.f, 0.f);
#pragma unroll 2
    for (int it = 0; it < 16; it++) {
        int r = it * 8 + rg;
        int d = didx[r], s = sidx[r];
        float4 tv = *(float4*)&tile[r * 132 + c4];
        float4 dx = *(const float4*)&Dx[d * HID + c4];
        float4 ex = *(const float4*)&Ex[s * HID + c4];
        float4 bx = *(const float4*)&Bx[s * HID + c4];
        float4 v;
        v.x = tv.x + bcv.x + dx.x + ex.x;
        v.y = tv.y + bcv.y + dx.y + ex.y;
        v.z = tv.z + bcv.z + dx.z + ex.z;
        v.w = tv.w + bcv.w + dx.w + ex.w;
        *(float4*)&C[(r0 + r) * HID + c4] = v;
        float4 sg;
        sg.x = 1.f / (1.f + __expf(-v.x));
        sg.y = 1.f / (1.f + __expf(-v.y));
        sg.z = 1.f / (1.f + __expf(-v.z));
        sg.w = 1.f / (1.f + __expf(-v.w));
        float4 nm = make_float4(sg.x * bx.x, sg.y * bx.y, sg.z * bx.z, sg.w * bx.w);
        red4(&g_num[d * HID + c4], nm);
        red4(&g_den[d * HID + c4], sg);
        s1v.x += v.x; s1v.y += v.y; s1v.z += v.z; s1v.w += v.w;
        s2v.x += v.x * v.x; s2v.y += v.y * v.y; s2v.z += v.z * v.z; s2v.w += v.w * v.w;
    }
    *(float4*)&sred[rg * 128 + c4] = s1v;
    *(float4*)&sred[1024 + rg * 128 + c4] = s2v;
    __syncthreads();
    if (doStats && tid < 128) {
        float a = 0.f, b = 0.f;
#pragma unroll
        for (int r2 = 0; r2 < 8; r2++) {
            a += sred[r2 * 128 + tid];
            b += sred[1024 + r2 * 128 + tid];
        }
        g_part[(blockIdx.x * HID + tid) * 2] = a;
        g_part[(blockIdx.x * HID + tid) * 2 + 1] = b;
    }
}

// ---------------- zero num/den ----------------
__global__ void zero_nd_kernel() {
    int i = blockIdx.x * blockDim.x + threadIdx.x;
    ((float4*)g_num)[i] = make_float4(0.f, 0.f, 0.f, 0.f);
    ((float4*)g_den)[i] = make_float4(0.f, 0.f, 0.f, 0.f);
}

// ---------------- h_new = Ax + num/(den+eps) fused with BN partials ----------------
__global__ void node_hnew_stats_kernel() {
    int c = threadIdx.x;
    float s = 0.f, ss = 0.f;
    for (int r = blockIdx.x; r < NND; r += gridDim.x) {
        int i = r * HID + c;
        float v = g_Ax[i] + g_num[i] / (g_den[i] + 1e-6f);
        g_Ax[i] = v;
        s += v; ss += v * v;
    }
    g_part[(blockIdx.x * HID + c) * 2] = s;
    g_part[(blockIdx.x * HID + c) * 2 + 1] = ss;
}

// ---------------- BN finalize ----------------
__global__ void bn_finalize2(int G, float invM, const float* __restrict__ gamma,
                             const float* __restrict__ beta,
                             float* __restrict__ scale, float* __restrict__ shift) {
    int c = blockIdx.x;
    int tid = threadIdx.x;
    double s = 0.0, ss = 0.0;
    for (int gi = tid; gi < G; gi += 256) {
        s  += (double)g_part[(gi * HID + c) * 2];
        ss += (double)g_part[(gi * HID + c) * 2 + 1];
    }
    __shared__ double rs[256], rss[256];
    rs[tid] = s; rss[tid] = ss;
    __syncthreads();
    for (int o = 128; o > 0; o >>= 1) {
        if (tid < o) { rs[tid] += rs[tid + o]; rss[tid] += rss[tid + o]; }
        __syncthreads();
    }
    if (tid == 0) {
        double mu = rs[0] * (double)invM;
        double var = rss[0] * (double)invM - mu * mu;
        float inv = rsqrtf((float)var + 1e-5f);
        float scv = gamma[c] * inv;
        scale[c] = scv;
        shift[c] = beta[c] - (float)mu * scv;
    }
}

// ---------------- BN apply + relu + residual (nodes) ----------------
__global__ void bn_apply_kernel(const float* __restrict__ v, const float* __restrict__ scale,
                                const float* __restrict__ shift, const float* __restrict__ resid,
                                float* __restrict__ out, int n4) {
    int i = blockIdx.x * blockDim.x + threadIdx.x;
    if (i >= n4) return;
    int c4 = i & 31;
    float4 vv = ((const float4*)v)[i];
    float4 rr = ((const float4*)resid)[i];
    float4 sc = ((const float4*)scale)[c4];
    float4 sh = ((const float4*)shift)[c4];
    float4 o;
    o.x = fmaxf(vv.x * sc.x + sh.x, 0.f) + rr.x;
    o.y = fmaxf(vv.y * sc.y + sh.y, 0.f) + rr.y;
    o.z = fmaxf(vv.z * sc.z + sh.z, 0.f) + rr.z;
    o.w = fmaxf(vv.w * sc.w + sh.w, 0.f) + rr.w;
    ((float4*)out)[i] = o;
}

// ---------------- dense attention per (head, batch graph) ----------------
__global__ void attn_kernel(const float* __restrict__ q, const float* __restrict__ k,
                            const float* __restrict__ v, const float* __restrict__ sph,
                            float* __restrict__ o) {
    extern __shared__ float smf[];
    float* ks = smf;
    float* vs = smf + 128 * 36;
    float* ps = smf + 2 * 128 * 36;
    int head = blockIdx.x, b = blockIdx.y;
    int s = threadIdx.x;
    int nodebase = (b * SEQ + s) * HID + head * 32;
    float qr[32];
#pragma unroll
    for (int d4 = 0; d4 < 8; d4++) {
        float4 tq = *(const float4*)&q[nodebase + d4 * 4];
        qr[d4 * 4] = tq.x; qr[d4 * 4 + 1] = tq.y; qr[d4 * 4 + 2] = tq.z; qr[d4 * 4 + 3] = tq.w;
        *(float4*)&ks[s * 36 + d4 * 4] = *(const float4*)&k[nodebase + d4 * 4];
        *(float4*)&vs[s * 36 + d4 * 4] = *(const float4*)&v[nodebase + d4 * 4];
    }
    __syncthreads();
    const float isd = 0.17677669529663687f;
    for (int t = 0; t < SEQ; t++) {
        float acc = 0.f;
#pragma unroll
        for (int d4 = 0; d4 < 8; d4++) {
            float4 kk = *(float4*)&ks[t * 36 + d4 * 4];
            acc += qr[d4 * 4] * kk.x + qr[d4 * 4 + 1] * kk.y +
                   qr[d4 * 4 + 2] * kk.z + qr[d4 * 4 + 3] * kk.w;
        }
        ps[s * 133 + t] = acc * isd;
    }
    __syncthreads();
    const float* sb = sph + b * SEQ * SEQ;
    for (int i = s; i < SEQ * SEQ; i += 128) {
        int s2 = i >> 7, t2 = i & 127;
        ps[s2 * 133 + t2] *= sb[i];
    }
    __syncthreads();
    float mx = -1e30f;
    for (int t = 0; t < SEQ; t++) mx = fmaxf(mx, ps[s * 133 + t]);
    float sum = 0.f;
    for (int t = 0; t < SEQ; t++) {
        float e = __expf(ps[s * 133 + t] - mx);
        ps[s * 133 + t] = e;
        sum += e;
    }
    float inv = 1.f / sum;
    float acc[32];
#pragma unroll
    for (int d = 0; d < 32; d++) acc[d] = 0.f;
    for (int t = 0; t < SEQ; t++) {
        float p = ps[s * 133 + t] * inv;
#pragma unroll
        for (int d4 = 0; d4 < 8; d4++) {
            float4 vvv = *(float4*)&vs[t * 36 + d4 * 4];
            acc[d4 * 4] += p * vvv.x; acc[d4 * 4 + 1] += p * vvv.y;
            acc[d4 * 4 + 2] += p * vvv.z; acc[d4 * 4 + 3] += p * vvv.w;
        }
    }
#pragma unroll
    for (int d4 = 0; d4 < 8; d4++) {
        float4 t4 = make_float4(acc[d4 * 4], acc[d4 * 4 + 1], acc[d4 * 4 + 2], acc[d4 * 4 + 3]);
        *(float4*)&o[nodebase + d4 * 4] = t4;
    }
}

// ---------------- mean pool + tiny MLP ----------------
__global__ void pool_kernel() {
    int b = blockIdx.x, c = threadIdx.x;
    float s = 0.f;
    for (int i = 0; i < SEQ; i++) s += g_h[(b * SEQ + i) * HID + c];
    g_pool[b * HID + c] = s * (1.f / 128.f);
}
__global__ void mlp_kernel(const float* __restrict__ in, const float* __restrict__ W,
                           const float* __restrict__ bias, float* __restrict__ out,
                           int K, int Ncol, int doRelu) {
    int r = blockIdx.x;
    __shared__ float xs[128];
    if ((int)threadIdx.x < K) xs[threadIdx.x] = in[r * K + threadIdx.x];
    __syncthreads();
    int c = threadIdx.x;
    if (c < Ncol) {
        float acc = bias[c];
        for (int k = 0; k < K; k++) acc += xs[k] * W[k * Ncol + c];
        if (doRelu) acc = fmaxf(acc, 0.f);
        out[r * Ncol + c] = acc;
    }
}

// ---------------- launch ----------------
extern "C" void kernel_launch(void* const* d_in, const int* in_sizes, int n_in,
                              void* d_out, int out_size) {
    const float* x        = (const float*)d_in[0];
    const float* pe       = (const float*)d_in[1];
    const float* edge_attr= (const float*)d_in[2];
    const float* sph      = (const float*)d_in[3];
    const float* node_w   = (const float*)d_in[4];
    const float* node_b   = (const float*)d_in[5];
    const float* pe_w     = (const float*)d_in[6];
    const float* pe_b     = (const float*)d_in[7];
    const float* Aw       = (const float*)d_in[8];
    const float* Ab       = (const float*)d_in[9];
    const float* Bw       = (const float*)d_in[10];
    const float* Bb       = (const float*)d_in[11];
    const float* Cw       = (const float*)d_in[12];
    const float* Cb       = (const float*)d_in[13];
    const float* Dw       = (const float*)d_in[14];
    const float* Db       = (const float*)d_in[15];
    const float* Ew       = (const float*)d_in[16];
    const float* Eb       = (const float*)d_in[17];
    const float* bnxg     = (const float*)d_in[18];
    const float* bnxb     = (const float*)d_in[19];
    const float* bneg     = (const float*)d_in[20];
    const float* bneb     = (const float*)d_in[21];
    const float* attw     = (const float*)d_in[22];
    const float* attb     = (const float*)d_in[23];
    const float* m1w      = (const float*)d_in[24];
    const float* m1b      = (const float*)d_in[25];
    const float* m2w      = (const float*)d_in[26];
    const float* m2b      = (const float*)d_in[27];
    const float* m3w      = (const float*)d_in[28];
    const float* m3b      = (const float*)d_in[29];
    const int*   ei       = (const int*)d_in[30];
    float* out = (float*)d_out;

    float *p_h, *p_e, *p_eij, *p_Ax, *p_Bx, *p_Dx, *p_Ex;
    float *p_scN, *p_shN, *p_scE, *p_shE, *p_pool, *p_t1, *p_t2;
    cudaGetSymbolAddress((void**)&p_h,   g_h);
    cudaGetSymbolAddress((void**)&p_e,   g_e);
    cudaGetSymbolAddress((void**)&p_eij, g_eij);
    cudaGetSymbolAddress((void**)&p_Ax,  g_Ax);
    cudaGetSymbolAddress((void**)&p_Bx,  g_Bx);
    cudaGetSymbolAddress((void**)&p_Dx,  g_Dx);
    cudaGetSymbolAddress((void**)&p_Ex,  g_Ex);
    cudaGetSymbolAddress((void**)&p_scN, g_scN);
    cudaGetSymbolAddress((void**)&p_shN, g_shN);
    cudaGetSymbolAddress((void**)&p_scE, g_scE);
    cudaGetSymbolAddress((void**)&p_shE, g_shE);
    cudaGetSymbolAddress((void**)&p_pool,g_pool);
    cudaGetSymbolAddress((void**)&p_t1,  g_t1);
    cudaGetSymbolAddress((void**)&p_t2,  g_t2);

    const int* src = ei;
    const int* dst = ei + NE;
    const int ATTN_SMEM = (2 * 128 * 36 + 128 * 133) * 4;
    const int PLAIN_SMEM = 17408 * 4;               // 69632
    const int EDGE_SMEM = (17408 + 256 + 2048) * 4; // 78848
    cudaFuncSetAttribute(attn_kernel, cudaFuncAttributeMaxDynamicSharedMemorySize, ATTN_SMEM);
    cudaFuncSetAttribute(gemm_tc_plain, cudaFuncAttributeMaxDynamicSharedMemorySize, PLAIN_SMEM);
    cudaFuncSetAttribute(gemm_tc_edge, cudaFuncAttributeMaxDynamicSharedMemorySize, EDGE_SMEM);

    input_proj_kernel<<<NND, 128>>>(x, pe, node_w, node_b, pe_w, pe_b);

    for (int l = 0; l < NL; l++) {
        zero_nd_kernel<<<NND * HID / 4 / 256, 256>>>();
        dim3 g4(NND / 128, 4);
        gemm_tc_plain<<<g4, 256, PLAIN_SMEM>>>(p_h,
            Aw + l * WSZ, Bw + l * WSZ, Dw + l * WSZ, Ew + l * WSZ,
            Ab + l * HID, Bb + l * HID, Db + l * HID, Eb + l * HID,
            p_Ax, p_Bx, p_Dx, p_Ex);
        const float* eA    = (l == 0) ? edge_attr : p_eij;
        const float* foldE = (l == 0) ? nullptr : ((l == 1) ? edge_attr : p_e);
        gemm_tc_edge<<<NE / 128, 256, EDGE_SMEM>>>(
            eA, foldE, p_e, Cw + l * WSZ, Cb + l * HID, p_eij,
            p_Dx, p_Ex, p_Bx, src, dst, (l < 3) ? 1 : 0);
        if (l < 3)
            bn_finalize2<<<HID, 256>>>(2048, 1.f / NE, bneg + l * HID, bneb + l * HID, p_scE, p_shE);
        node_hnew_stats_kernel<<<256, 128>>>();
        bn_finalize2<<<HID, 256>>>(256, 1.f / NND, bnxg + l * HID, bnxb + l * HID, p_scN, p_shN);
        bn_apply_kernel<<<(NND * 32) / 256, 256>>>(p_Ax, p_scN, p_shN, p_h, p_h, NND * 32);
        dim3 g3(NND / 128, 3);
        gemm_tc_plain<<<g3, 256, PLAIN_SMEM>>>(p_h,
            attw + 0 * WSZ, attw + 1 * WSZ, attw + 2 * WSZ, attw + 2 * WSZ,
            attb + 0 * HID, attb + 1 * HID, attb + 2 * HID, attb + 2 * HID,
            p_Ax, p_Bx, p_Dx, p_Dx);
        dim3 ag(4, BATCH);
        attn_kernel<<<ag, 128, ATTN_SMEM>>>(p_Ax, p_Bx, p_Dx, sph, p_Ex);
        dim3 g1(NND / 128, 1);
        gemm_tc_plain<<<g1, 256, PLAIN_SMEM>>>(p_Ex,
            attw + 3 * WSZ, attw + 3 * WSZ, attw + 3 * WSZ, attw + 3 * WSZ,
            attb + 3 * HID, attb + 3 * HID, attb + 3 * HID, attb + 3 * HID,
            p_h, p_h, p_h, p_h);
    }
    pool_kernel<<<BATCH, 128>>>();
    mlp_kernel<<<BATCH, 128>>>(p_pool, m1w, m1b, p_t1, 128, 64, 1);
    mlp_kernel<<<BATCH, 128>>>(p_t1, m2w, m2b, p_t2, 64, 32, 1);
    mlp_kernel<<<BATCH, 128>>>(p_t2, m3w, m3b, out, 32, 10, 0);
}

// round 5
// speedup vs baseline: 2.1618x; 1.0436x over previous
#include <cuda_runtime.h>
#include <cstdint>

#define NND 16384
#define NE  262144
#define HID 128
#define BATCH 128
#define SEQ 128
#define NL 4
#define WSZ (HID*HID)

// ---------------- scratch ----------------
__device__ float g_h[NND * HID];
__device__ float g_e[NE * HID];
__device__ float g_eij[NE * HID];
__device__ float g_Ax[NND * HID];
__device__ float g_Bx[NND * HID];
__device__ float g_Dx[NND * HID];
__device__ float g_Ex[NND * HID];
__device__ float g_num[NND * HID];
__device__ float g_den[NND * HID];
__device__ float g_part[2048 * HID * 2];
__device__ float g_scN[HID], g_shN[HID], g_scE[HID], g_shE[HID];
__device__ float g_pool[BATCH * HID];
__device__ float g_t1[BATCH * 64];
__device__ float g_t2[BATCH * 32];
// edge sort
__device__ int g_cnt[NND];
__device__ int g_src2[NE];
__device__ int g_dst2[NE];
__device__ int g_perm[NE];

__device__ __forceinline__ unsigned f2tf(float f) {
    unsigned u; asm("cvt.rna.tf32.f32 %0, %1;" : "=r"(u) : "f"(f)); return u;
}
__device__ __forceinline__ void tfsplit(float f, unsigned& hi, unsigned& lo) {
    hi = f2tf(f);
    lo = f2tf(f - __uint_as_float(hi));
}
__device__ __forceinline__ void mma8(float* d, const unsigned* a, const unsigned* b) {
    asm volatile("mma.sync.aligned.m16n8k8.row.col.f32.tf32.tf32.f32 "
        "{%0,%1,%2,%3}, {%4,%5,%6,%7}, {%8,%9}, {%0,%1,%2,%3};"
        : "+f"(d[0]), "+f"(d[1]), "+f"(d[2]), "+f"(d[3])
        : "r"(a[0]), "r"(a[1]), "r"(a[2]), "r"(a[3]), "r"(b[0]), "r"(b[1]));
}
__device__ __forceinline__ void red4(float* p, float4 v) {
    asm volatile("red.global.add.v4.f32 [%0], {%1,%2,%3,%4};"
        :: "l"(p), "f"(v.x), "f"(v.y), "f"(v.z), "f"(v.w) : "memory");
}

// ---------------- edge counting sort ----------------
__global__ void hist_zero_kernel() {
    int i = blockIdx.x * blockDim.x + threadIdx.x;
    if (i < NND) g_cnt[i] = 0;
}
__global__ void hist_kernel(const int* __restrict__ dst) {
    int i = blockIdx.x * blockDim.x + threadIdx.x;
    if (i < NE) atomicAdd(&g_cnt[dst[i]], 1);
}
__global__ __launch_bounds__(1024) void scan_kernel() {
    __shared__ int ssum[1024];
    int tid = threadIdx.x;
    int base = tid * 16;
    int loc[16]; int s = 0;
#pragma unroll
    for (int i = 0; i < 16; i++) { loc[i] = s; s += g_cnt[base + i]; }
    ssum[tid] = s;
    __syncthreads();
    for (int off = 1; off < 1024; off <<= 1) {
        int v = (tid >= off) ? ssum[tid - off] : 0;
        __syncthreads();
        ssum[tid] += v;
        __syncthreads();
    }
    int pre = (tid == 0) ? 0 : ssum[tid - 1];
#pragma unroll
    for (int i = 0; i < 16; i++) g_cnt[base + i] = pre + loc[i];
}
__global__ void scatter_kernel(const int* __restrict__ src, const int* __restrict__ dst) {
    int i = blockIdx.x * blockDim.x + threadIdx.x;
    if (i >= NE) return;
    int d = dst[i];
    int pos = atomicAdd(&g_cnt[d], 1);
    g_perm[pos] = i;
    g_src2[pos] = src[i];
    g_dst2[pos] = d;
}

// ---------------- input projection ----------------
__global__ void input_proj_kernel(const float* __restrict__ x, const float* __restrict__ pe,
                                  const float* __restrict__ nw, const float* __restrict__ nb,
                                  const float* __restrict__ pw, const float* __restrict__ pb) {
    int row = blockIdx.x;
    int c = threadIdx.x;
    __shared__ float xs[64];
    __shared__ float ps[16];
    if (c < 64) xs[c] = x[row * 64 + c];
    else if (c < 80) ps[c - 64] = pe[row * 16 + (c - 64)];
    __syncthreads();
    float acc;
    if (c < 112) {
        acc = nb[c];
#pragma unroll
        for (int k = 0; k < 64; k++) acc += xs[k] * nw[k * 112 + c];
    } else {
        int cc = c - 112;
        acc = pb[cc];
#pragma unroll
        for (int k = 0; k < 16; k++) acc += ps[k] * pw[k * 16 + cc];
    }
    g_h[row * HID + c] = acc;
}

// ================= 3xTF32 tensor-core GEMM: plain, multi-weight via blockIdx.y =================
__global__ __launch_bounds__(256, 2) void gemm_tc_plain(
    const float* __restrict__ A,
    const float* __restrict__ W0, const float* __restrict__ W1,
    const float* __restrict__ W2, const float* __restrict__ W3,
    const float* __restrict__ b0, const float* __restrict__ b1,
    const float* __restrict__ b2, const float* __restrict__ b3,
    float* __restrict__ C0, float* __restrict__ C1,
    float* __restrict__ C2, float* __restrict__ C3) {
    int y = blockIdx.y;
    const float* W = (y == 0) ? W0 : (y == 1) ? W1 : (y == 2) ? W2 : W3;
    const float* bb = (y == 0) ? b0 : (y == 1) ? b1 : (y == 2) ? b2 : b3;
    float* C = (y == 0) ? C0 : (y == 1) ? C1 : (y == 2) ? C2 : C3;

    extern __shared__ unsigned sm[];
    unsigned* AsH = sm;
    unsigned* AsL = sm + 4352;
    unsigned* WsH = sm + 8704;
    unsigned* WsL = sm + 13056;

    int tid = threadIdx.x, lane = tid & 31, wid = tid >> 5;
    int wm = wid & 3, wn = wid >> 2, g = lane >> 2, t = lane & 3;
    int r0 = blockIdx.x * 128;

    float acc[2][8][4];
#pragma unroll
    for (int i = 0; i < 2; i++)
#pragma unroll
        for (int j = 0; j < 8; j++)
#pragma unroll
            for (int q = 0; q < 4; q++) acc[i][j][q] = 0.f;

    int arow = tid >> 1, acb = (tid & 1) * 16;
    int wrow = tid >> 3, wcb = (tid & 7) * 16;

    for (int k0 = 0; k0 < 128; k0 += 32) {
#pragma unroll
        for (int q = 0; q < 4; q++) {
            int kc = acb + q * 4;
            float4 av = *(const float4*)&A[(r0 + arow) * HID + k0 + kc];
            unsigned h, l;
            tfsplit(av.x, h, l); AsH[(kc + 0) * 136 + arow] = h; AsL[(kc + 0) * 136 + arow] = l;
            tfsplit(av.y, h, l); AsH[(kc + 1) * 136 + arow] = h; AsL[(kc + 1) * 136 + arow] = l;
            tfsplit(av.z, h, l); AsH[(kc + 2) * 136 + arow] = h; AsL[(kc + 2) * 136 + arow] = l;
            tfsplit(av.w, h, l); AsH[(kc + 3) * 136 + arow] = h; AsL[(kc + 3) * 136 + arow] = l;
            float4 wv = *(const float4*)&W[(k0 + wrow) * HID + wcb + q * 4];
            int wp = wrow * 136 + wcb + q * 4;
            tfsplit(wv.x, h, l); WsH[wp + 0] = h; WsL[wp + 0] = l;
            tfsplit(wv.y, h, l); WsH[wp + 1] = h; WsL[wp + 1] = l;
            tfsplit(wv.z, h, l); WsH[wp + 2] = h; WsL[wp + 2] = l;
            tfsplit(wv.w, h, l); WsH[wp + 3] = h; WsL[wp + 3] = l;
        }
        __syncthreads();
#pragma unroll
        for (int kk = 0; kk < 32; kk += 8) {
            int ka = (kk + t) * 136, kb = (kk + t + 4) * 136;
            unsigned ah[2][4], al[2][4];
#pragma unroll
            for (int mt = 0; mt < 2; mt++) {
                int rb = wm * 32 + mt * 16 + g;
                ah[mt][0] = AsH[ka + rb]; ah[mt][1] = AsH[ka + rb + 8];
                ah[mt][2] = AsH[kb + rb]; ah[mt][3] = AsH[kb + rb + 8];
                al[mt][0] = AsL[ka + rb]; al[mt][1] = AsL[ka + rb + 8];
                al[mt][2] = AsL[kb + rb]; al[mt][3] = AsL[kb + rb + 8];
            }
#pragma unroll
            for (int nt = 0; nt < 8; nt++) {
                int cb = wn * 64 + nt * 8 + g;
                unsigned bh[2] = { WsH[ka + cb], WsH[kb + cb] };
                unsigned bl[2] = { WsL[ka + cb], WsL[kb + cb] };
#pragma unroll
                for (int mt = 0; mt < 2; mt++) {
                    mma8(acc[mt][nt], ah[mt], bh);
                    mma8(acc[mt][nt], al[mt], bh);
                    mma8(acc[mt][nt], ah[mt], bl);
                }
            }
        }
        __syncthreads();
    }
#pragma unroll
    for (int mt = 0; mt < 2; mt++) {
#pragma unroll
        for (int nt = 0; nt < 8; nt++) {
            int c = wn * 64 + nt * 8 + 2 * t;
            float bx = bb[c], by = bb[c + 1];
            int r = r0 + wm * 32 + mt * 16 + g;
            *(float2*)&C[r * HID + c] = make_float2(acc[mt][nt][0] + bx, acc[mt][nt][1] + by);
            *(float2*)&C[(r + 8) * HID + c] = make_float2(acc[mt][nt][2] + bx, acc[mt][nt][3] + by);
        }
    }
}

// ================= edge GEMM (sorted edges): BN-fold loader + segment-reduce epilogue =================
__global__ __launch_bounds__(256, 2) void gemm_tc_edge(
    const float* A, const float* __restrict__ foldE, float* __restrict__ foldOut,
    const float* __restrict__ W, const float* __restrict__ bias,
    float* C,
    const float* __restrict__ Dx, const float* __restrict__ Ex, const float* __restrict__ Bx,
    int doStats, int permA, int permF, int writeC, int writeFold) {
    extern __shared__ unsigned sm[];
    unsigned* AsH = sm;
    unsigned* AsL = sm + 4352;
    unsigned* WsH = sm + 8704;
    unsigned* WsL = sm + 13056;           // operand region ends at 17408
    float* tile = (float*)sm;             // overlay 128x132 after mainloop
    int* sidx = (int*)(sm + 17408);
    int* didx = sidx + 128;
    int* pidx = didx + 128;
    float* sred = (float*)(pidx + 128);   // 2048 floats

    int tid = threadIdx.x, lane = tid & 31, wid = tid >> 5;
    int wm = wid & 3, wn = wid >> 2, g = lane >> 2, t = lane & 3;
    int r0 = blockIdx.x * 128;

    if (tid < 128) {
        sidx[tid] = g_src2[r0 + tid];
        didx[tid] = g_dst2[r0 + tid];
        pidx[tid] = g_perm[r0 + tid];
    }
    __syncthreads();

    float acc[2][8][4];
#pragma unroll
    for (int i = 0; i < 2; i++)
#pragma unroll
        for (int j = 0; j < 8; j++)
#pragma unroll
            for (int q = 0; q < 4; q++) acc[i][j][q] = 0.f;

    int arow = tid >> 1, acb = (tid & 1) * 16;
    int wrow = tid >> 3, wcb = (tid & 7) * 16;
    bool fold = (foldE != nullptr);
    int aIdx = permA ? pidx[arow] : (r0 + arow);
    int fIdx = permF ? pidx[arow] : (r0 + arow);

    for (int k0 = 0; k0 < 128; k0 += 32) {
#pragma unroll
        for (int q = 0; q < 4; q++) {
            int kc = acb + q * 4;
            float4 av = *(const float4*)&A[aIdx * HID + k0 + kc];
            if (fold) {
                float4 ev = *(const float4*)&foldE[fIdx * HID + k0 + kc];
                float4 sc = *(const float4*)&g_scE[k0 + kc];
                float4 sh = *(const float4*)&g_shE[k0 + kc];
                av.x = fmaxf(av.x * sc.x + sh.x, 0.f) + ev.x;
                av.y = fmaxf(av.y * sc.y + sh.y, 0.f) + ev.y;
                av.z = fmaxf(av.z * sc.z + sh.z, 0.f) + ev.z;
                av.w = fmaxf(av.w * sc.w + sh.w, 0.f) + ev.w;
                if (writeFold) *(float4*)&foldOut[(r0 + arow) * HID + k0 + kc] = av;
            }
            unsigned h, l;
            tfsplit(av.x, h, l); AsH[(kc + 0) * 136 + arow] = h; AsL[(kc + 0) * 136 + arow] = l;
            tfsplit(av.y, h, l); AsH[(kc + 1) * 136 + arow] = h; AsL[(kc + 1) * 136 + arow] = l;
            tfsplit(av.z, h, l); AsH[(kc + 2) * 136 + arow] = h; AsL[(kc + 2) * 136 + arow] = l;
            tfsplit(av.w, h, l); AsH[(kc + 3) * 136 + arow] = h; AsL[(kc + 3) * 136 + arow] = l;
            float4 wv = *(const float4*)&W[(k0 + wrow) * HID + wcb + q * 4];
            int wp = wrow * 136 + wcb + q * 4;
            tfsplit(wv.x, h, l); WsH[wp + 0] = h; WsL[wp + 0] = l;
            tfsplit(wv.y, h, l); WsH[wp + 1] = h; WsL[wp + 1] = l;
            tfsplit(wv.z, h, l); WsH[wp + 2] = h; WsL[wp + 2] = l;
            tfsplit(wv.w, h, l); WsH[wp + 3] = h; WsL[wp + 3] = l;
        }
        __syncthreads();
#pragma unroll
        for (int kk = 0; kk < 32; kk += 8) {
            int ka = (kk + t) * 136, kb = (kk + t + 4) * 136;
            unsigned ah[2][4], al[2][4];
#pragma unroll
            for (int mt = 0; mt < 2; mt++) {
                int rb = wm * 32 + mt * 16 + g;
                ah[mt][0] = AsH[ka + rb]; ah[mt][1] = AsH[ka + rb + 8];
                ah[mt][2] = AsH[kb + rb]; ah[mt][3] = AsH[kb + rb + 8];
                al[mt][0] = AsL[ka + rb]; al[mt][1] = AsL[ka + rb + 8];
                al[mt][2] = AsL[kb + rb]; al[mt][3] = AsL[kb + rb + 8];
            }
#pragma unroll
            for (int nt = 0; nt < 8; nt++) {
                int cb = wn * 64 + nt * 8 + g;
                unsigned bh[2] = { WsH[ka + cb], WsH[kb + cb] };
                unsigned bl[2] = { WsL[ka + cb], WsL[kb + cb] };
#pragma unroll
                for (int mt = 0; mt < 2; mt++) {
                    mma8(acc[mt][nt], ah[mt], bh);
                    mma8(acc[mt][nt], al[mt], bh);
                    mma8(acc[mt][nt], ah[mt], bl);
                }
            }
        }
        __syncthreads();
    }
    // stage accumulators to smem tile
#pragma unroll
    for (int mt = 0; mt < 2; mt++) {
#pragma unroll
        for (int nt = 0; nt < 8; nt++) {
            int c = wn * 64 + nt * 8 + 2 * t;
            int r = wm * 32 + mt * 16 + g;
            tile[r * 132 + c] = acc[mt][nt][0];
            tile[r * 132 + c + 1] = acc[mt][nt][1];
            tile[(r + 8) * 132 + c] = acc[mt][nt][2];
            tile[(r + 8) * 132 + c + 1] = acc[mt][nt][3];
        }
    }
    __syncthreads();
    // epilogue: warp = 16 contiguous sorted rows, lane = 4 channels; segment-reduce on dst runs
    {
        int c4 = (tid & 31) * 4;
        int chunk = tid >> 5;  // 0..7
        float4 bcv = *(const float4*)&bias[c4];
        float4 s1v = make_float4(0.f, 0.f, 0.f, 0.f);
        float4 s2v = make_float4(0.f, 0.f, 0.f, 0.f);
        float4 accN = make_float4(0.f, 0.f, 0.f, 0.f);
        float4 accD = make_float4(0.f, 0.f, 0.f, 0.f);
        int curd = didx[chunk * 16];
#pragma unroll 4
        for (int rr = 0; rr < 16; rr++) {
            int r = chunk * 16 + rr;
            int d = didx[r], s = sidx[r];
            if (d != curd) {
                red4(&g_num[curd * HID + c4], accN);
                red4(&g_den[curd * HID + c4], accD);
                accN = make_float4(0.f, 0.f, 0.f, 0.f);
                accD = make_float4(0.f, 0.f, 0.f, 0.f);
                curd = d;
            }
            float4 tv = *(float4*)&tile[r * 132 + c4];
            float4 dx = *(const float4*)&Dx[d * HID + c4];
            float4 ex = *(const float4*)&Ex[s * HID + c4];
            float4 bx = *(const float4*)&Bx[s * HID + c4];
            float4 v;
            v.x = tv.x + bcv.x + dx.x + ex.x;
            v.y = tv.y + bcv.y + dx.y + ex.y;
            v.z = tv.z + bcv.z + dx.z + ex.z;
            v.w = tv.w + bcv.w + dx.w + ex.w;
            if (writeC) *(float4*)&C[(r0 + r) * HID + c4] = v;
            float4 sg;
            sg.x = 1.f / (1.f + __expf(-v.x));
            sg.y = 1.f / (1.f + __expf(-v.y));
            sg.z = 1.f / (1.f + __expf(-v.z));
            sg.w = 1.f / (1.f + __expf(-v.w));
            accN.x += sg.x * bx.x; accN.y += sg.y * bx.y;
            accN.z += sg.z * bx.z; accN.w += sg.w * bx.w;
            accD.x += sg.x; accD.y += sg.y; accD.z += sg.z; accD.w += sg.w;
            s1v.x += v.x; s1v.y += v.y; s1v.z += v.z; s1v.w += v.w;
            s2v.x += v.x * v.x; s2v.y += v.y * v.y; s2v.z += v.z * v.z; s2v.w += v.w * v.w;
        }
        red4(&g_num[curd * HID + c4], accN);
        red4(&g_den[curd * HID + c4], accD);
        if (doStats) {
            *(float4*)&sred[chunk * 128 + c4] = s1v;
            *(float4*)&sred[1024 + chunk * 128 + c4] = s2v;
        }
    }
    __syncthreads();
    if (doStats && tid < 128) {
        float a = 0.f, b = 0.f;
#pragma unroll
        for (int r2 = 0; r2 < 8; r2++) {
            a += sred[r2 * 128 + tid];
            b += sred[1024 + r2 * 128 + tid];
        }
        g_part[(blockIdx.x * HID + tid) * 2] = a;
        g_part[(blockIdx.x * HID + tid) * 2 + 1] = b;
    }
}

// ---------------- zero num/den ----------------
__global__ void zero_nd_kernel() {
    int i = blockIdx.x * blockDim.x + threadIdx.x;
    ((float4*)g_num)[i] = make_float4(0.f, 0.f, 0.f, 0.f);
    ((float4*)g_den)[i] = make_float4(0.f, 0.f, 0.f, 0.f);
}

// ---------------- h_new = Ax + num/(den+eps) fused with BN partials ----------------
__global__ void node_hnew_stats_kernel() {
    int c = threadIdx.x;
    float s = 0.f, ss = 0.f;
    for (int r = blockIdx.x; r < NND; r += gridDim.x) {
        int i = r * HID + c;
        float v = g_Ax[i] + g_num[i] / (g_den[i] + 1e-6f);
        g_Ax[i] = v;
        s += v; ss += v * v;
    }
    g_part[(blockIdx.x * HID + c) * 2] = s;
    g_part[(blockIdx.x * HID + c) * 2 + 1] = ss;
}

// ---------------- BN finalize ----------------
__global__ void bn_finalize2(int G, float invM, const float* __restrict__ gamma,
                             const float* __restrict__ beta,
                             float* __restrict__ scale, float* __restrict__ shift) {
    int c = blockIdx.x;
    int tid = threadIdx.x;
    double s = 0.0, ss = 0.0;
    for (int gi = tid; gi < G; gi += 256) {
        s  += (double)g_part[(gi * HID + c) * 2];
        ss += (double)g_part[(gi * HID + c) * 2 + 1];
    }
    __shared__ double rs[256], rss[256];
    rs[tid] = s; rss[tid] = ss;
    __syncthreads();
    for (int o = 128; o > 0; o >>= 1) {
        if (tid < o) { rs[tid] += rs[tid + o]; rss[tid] += rss[tid + o]; }
        __syncthreads();
    }
    if (tid == 0) {
        double mu = rs[0] * (double)invM;
        double var = rss[0] * (double)invM - mu * mu;
        float inv = rsqrtf((float)var + 1e-5f);
        float scv = gamma[c] * inv;
        scale[c] = scv;
        shift[c] = beta[c] - (float)mu * scv;
    }
}

// ---------------- BN apply + relu + residual (nodes) ----------------
__global__ void bn_apply_kernel(const float* __restrict__ v, const float* __restrict__ scale,
                                const float* __restrict__ shift, const float* __restrict__ resid,
                                float* __restrict__ out, int n4) {
    int i = blockIdx.x * blockDim.x + threadIdx.x;
    if (i >= n4) return;
    int c4 = i & 31;
    float4 vv = ((const float4*)v)[i];
    float4 rr = ((const float4*)resid)[i];
    float4 sc = ((const float4*)scale)[c4];
    float4 sh = ((const float4*)shift)[c4];
    float4 o;
    o.x = fmaxf(vv.x * sc.x + sh.x, 0.f) + rr.x;
    o.y = fmaxf(vv.y * sc.y + sh.y, 0.f) + rr.y;
    o.z = fmaxf(vv.z * sc.z + sh.z, 0.f) + rr.z;
    o.w = fmaxf(vv.w * sc.w + sh.w, 0.f) + rr.w;
    ((float4*)out)[i] = o;
}

// ---------------- dense attention per (head, batch graph) ----------------
__global__ void attn_kernel(const float* __restrict__ q, const float* __restrict__ k,
                            const float* __restrict__ v, const float* __restrict__ sph,
                            float* __restrict__ o) {
    extern __shared__ float smf[];
    float* ks = smf;
    float* vs = smf + 128 * 36;
    float* ps = smf + 2 * 128 * 36;
    int head = blockIdx.x, b = blockIdx.y;
    int s = threadIdx.x;
    int nodebase = (b * SEQ + s) * HID + head * 32;
    float qr[32];
#pragma unroll
    for (int d4 = 0; d4 < 8; d4++) {
        float4 tq = *(const float4*)&q[nodebase + d4 * 4];
        qr[d4 * 4] = tq.x; qr[d4 * 4 + 1] = tq.y; qr[d4 * 4 + 2] = tq.z; qr[d4 * 4 + 3] = tq.w;
        *(float4*)&ks[s * 36 + d4 * 4] = *(const float4*)&k[nodebase + d4 * 4];
        *(float4*)&vs[s * 36 + d4 * 4] = *(const float4*)&v[nodebase + d4 * 4];
    }
    __syncthreads();
    const float isd = 0.17677669529663687f;
    for (int t = 0; t < SEQ; t++) {
        float acc = 0.f;
#pragma unroll
        for (int d4 = 0; d4 < 8; d4++) {
            float4 kk = *(float4*)&ks[t * 36 + d4 * 4];
            acc += qr[d4 * 4] * kk.x + qr[d4 * 4 + 1] * kk.y +
                   qr[d4 * 4 + 2] * kk.z + qr[d4 * 4 + 3] * kk.w;
        }
        ps[s * 133 + t] = acc * isd;
    }
    __syncthreads();
    const float* sb = sph + b * SEQ * SEQ;
    for (int i = s; i < SEQ * SEQ; i += 128) {
        int s2 = i >> 7, t2 = i & 127;
        ps[s2 * 133 + t2] *= sb[i];
    }
    __syncthreads();
    float mx = -1e30f;
    for (int t = 0; t < SEQ; t++) mx = fmaxf(mx, ps[s * 133 + t]);
    float sum = 0.f;
    for (int t = 0; t < SEQ; t++) {
        float e = __expf(ps[s * 133 + t] - mx);
        ps[s * 133 + t] = e;
        sum += e;
    }
    float inv = 1.f / sum;
    float acc[32];
#pragma unroll
    for (int d = 0; d < 32; d++) acc[d] = 0.f;
    for (int t = 0; t < SEQ; t++) {
        float p = ps[s * 133 + t] * inv;
#pragma unroll
        for (int d4 = 0; d4 < 8; d4++) {
            float4 vvv = *(float4*)&vs[t * 36 + d4 * 4];
            acc[d4 * 4] += p * vvv.x; acc[d4 * 4 + 1] += p * vvv.y;
            acc[d4 * 4 + 2] += p * vvv.z; acc[d4 * 4 + 3] += p * vvv.w;
        }
    }
#pragma unroll
    for (int d4 = 0; d4 < 8; d4++) {
        float4 t4 = make_float4(acc[d4 * 4], acc[d4 * 4 + 1], acc[d4 * 4 + 2], acc[d4 * 4 + 3]);
        *(float4*)&o[nodebase + d4 * 4] = t4;
    }
}

// ---------------- mean pool + tiny MLP ----------------
__global__ void pool_kernel() {
    int b = blockIdx.x, c = threadIdx.x;
    float s = 0.f;
    for (int i = 0; i < SEQ; i++) s += g_h[(b * SEQ + i) * HID + c];
    g_pool[b * HID + c] = s * (1.f / 128.f);
}
__global__ void mlp_kernel(const float* __restrict__ in, const float* __restrict__ W,
                           const float* __restrict__ bias, float* __restrict__ out,
                           int K, int Ncol, int doRelu) {
    int r = blockIdx.x;
    __shared__ float xs[128];
    if ((int)threadIdx.x < K) xs[threadIdx.x] = in[r * K + threadIdx.x];
    __syncthreads();
    int c = threadIdx.x;
    if (c < Ncol) {
        float acc = bias[c];
        for (int k = 0; k < K; k++) acc += xs[k] * W[k * Ncol + c];
        if (doRelu) acc = fmaxf(acc, 0.f);
        out[r * Ncol + c] = acc;
    }
}

// ---------------- launch ----------------
extern "C" void kernel_launch(void* const* d_in, const int* in_sizes, int n_in,
                              void* d_out, int out_size) {
    const float* x        = (const float*)d_in[0];
    const float* pe       = (const float*)d_in[1];
    const float* edge_attr= (const float*)d_in[2];
    const float* sph      = (const float*)d_in[3];
    const float* node_w   = (const float*)d_in[4];
    const float* node_b   = (const float*)d_in[5];
    const float* pe_w     = (const float*)d_in[6];
    const float* pe_b     = (const float*)d_in[7];
    const float* Aw       = (const float*)d_in[8];
    const float* Ab       = (const float*)d_in[9];
    const float* Bw       = (const float*)d_in[10];
    const float* Bb       = (const float*)d_in[11];
    const float* Cw       = (const float*)d_in[12];
    const float* Cb       = (const float*)d_in[13];
    const float* Dw       = (const float*)d_in[14];
    const float* Db       = (const float*)d_in[15];
    const float* Ew       = (const float*)d_in[16];
    const float* Eb       = (const float*)d_in[17];
    const float* bnxg     = (const float*)d_in[18];
    const float* bnxb     = (const float*)d_in[19];
    const float* bneg     = (const float*)d_in[20];
    const float* bneb     = (const float*)d_in[21];
    const float* attw     = (const float*)d_in[22];
    const float* attb     = (const float*)d_in[23];
    const float* m1w      = (const float*)d_in[24];
    const float* m1b      = (const float*)d_in[25];
    const float* m2w      = (const float*)d_in[26];
    const float* m2b      = (const float*)d_in[27];
    const float* m3w      = (const float*)d_in[28];
    const float* m3b      = (const float*)d_in[29];
    const int*   ei       = (const int*)d_in[30];
    float* out = (float*)d_out;

    float *p_h, *p_e, *p_eij, *p_Ax, *p_Bx, *p_Dx, *p_Ex;
    float *p_scN, *p_shN, *p_scE, *p_shE, *p_pool, *p_t1, *p_t2;
    cudaGetSymbolAddress((void**)&p_h,   g_h);
    cudaGetSymbolAddress((void**)&p_e,   g_e);
    cudaGetSymbolAddress((void**)&p_eij, g_eij);
    cudaGetSymbolAddress((void**)&p_Ax,  g_Ax);
    cudaGetSymbolAddress((void**)&p_Bx,  g_Bx);
    cudaGetSymbolAddress((void**)&p_Dx,  g_Dx);
    cudaGetSymbolAddress((void**)&p_Ex,  g_Ex);
    cudaGetSymbolAddress((void**)&p_scN, g_scN);
    cudaGetSymbolAddress((void**)&p_shN, g_shN);
    cudaGetSymbolAddress((void**)&p_scE, g_scE);
    cudaGetSymbolAddress((void**)&p_shE, g_shE);
    cudaGetSymbolAddress((void**)&p_pool,g_pool);
    cudaGetSymbolAddress((void**)&p_t1,  g_t1);
    cudaGetSymbolAddress((void**)&p_t2,  g_t2);

    const int* src = ei;
    const int* dst = ei + NE;
    const int ATTN_SMEM = (2 * 128 * 36 + 128 * 133) * 4;
    const int PLAIN_SMEM = 17408 * 4;               // 69632
    const int EDGE_SMEM = (17408 + 384 + 2048) * 4; // 79360
    cudaFuncSetAttribute(attn_kernel, cudaFuncAttributeMaxDynamicSharedMemorySize, ATTN_SMEM);
    cudaFuncSetAttribute(gemm_tc_plain, cudaFuncAttributeMaxDynamicSharedMemorySize, PLAIN_SMEM);
    cudaFuncSetAttribute(gemm_tc_edge, cudaFuncAttributeMaxDynamicSharedMemorySize, EDGE_SMEM);

    // edge counting sort by dst (once per call)
    hist_zero_kernel<<<NND / 256, 256>>>();
    hist_kernel<<<NE / 256, 256>>>(dst);
    scan_kernel<<<1, 1024>>>();
    scatter_kernel<<<NE / 256, 256>>>(src, dst);

    input_proj_kernel<<<NND, 128>>>(x, pe, node_w, node_b, pe_w, pe_b);

    for (int l = 0; l < NL; l++) {
        zero_nd_kernel<<<NND * HID / 4 / 256, 256>>>();
        dim3 g4(NND / 128, 4);
        gemm_tc_plain<<<g4, 256, PLAIN_SMEM>>>(p_h,
            Aw + l * WSZ, Bw + l * WSZ, Dw + l * WSZ, Ew + l * WSZ,
            Ab + l * HID, Bb + l * HID, Db + l * HID, Eb + l * HID,
            p_Ax, p_Bx, p_Dx, p_Ex);
        const float* eA    = (l == 0) ? edge_attr : p_eij;
        const float* foldE = (l == 0) ? nullptr : ((l == 1) ? edge_attr : p_e);
        int permA = (l == 0) ? 1 : 0;
        int permF = (l == 1) ? 1 : 0;
        int last = (l == NL - 1);
        gemm_tc_edge<<<NE / 128, 256, EDGE_SMEM>>>(
            eA, foldE, p_e, Cw + l * WSZ, Cb + l * HID, p_eij,
            p_Dx, p_Ex, p_Bx, last ? 0 : 1, permA, permF,
            last ? 0 : 1, last ? 0 : 1);
        if (!last)
            bn_finalize2<<<HID, 256>>>(2048, 1.f / NE, bneg + l * HID, bneb + l * HID, p_scE, p_shE);
        node_hnew_stats_kernel<<<1024, 128>>>();
        bn_finalize2<<<HID, 256>>>(1024, 1.f / NND, bnxg + l * HID, bnxb + l * HID, p_scN, p_shN);
        bn_apply_kernel<<<(NND * 32) / 256, 256>>>(p_Ax, p_scN, p_shN, p_h, p_h, NND * 32);
        dim3 g3(NND / 128, 3);
        gemm_tc_plain<<<g3, 256, PLAIN_SMEM>>>(p_h,
            attw + 0 * WSZ, attw + 1 * WSZ, attw + 2 * WSZ, attw + 2 * WSZ,
            attb + 0 * HID, attb + 1 * HID, attb + 2 * HID, attb + 2 * HID,
            p_Ax, p_Bx, p_Dx, p_Dx);
        dim3 ag(4, BATCH);
        attn_kernel<<<ag, 128, ATTN_SMEM>>>(p_Ax, p_Bx, p_Dx, sph, p_Ex);
        dim3 g1(NND / 128, 1);
        gemm_tc_plain<<<g1, 256, PLAIN_SMEM>>>(p_Ex,
            attw + 3 * WSZ, attw + 3 * WSZ, attw + 3 * WSZ, attw + 3 * WSZ,
            attb + 3 * HID, attb + 3 * HID, attb + 3 * HID, attb + 3 * HID,
            p_h, p_h, p_h, p_h);
    }
    pool_kernel<<<BATCH, 128>>>();
    mlp_kernel<<<BATCH, 128>>>(p_pool, m1w, m1b, p_t1, 128, 64, 1);
    mlp_kernel<<<BATCH, 128>>>(p_t1, m2w, m2b, p_t2, 64, 32, 1);
    mlp_kernel<<<BATCH, 128>>>(p_t2, m3w, m3b, out, 32, 10, 0);
}

// round 6
// speedup vs baseline: 2.2089x; 1.0218x over previous
#include <cuda_runtime.h>
#include <cstdint>

#define NND 16384
#define NE  262144
#define HID 128
#define BATCH 128
#define SEQ 128
#define NL 4
#define WSZ (HID*HID)

// smem stage layout (words)
#define STAGE 13568
#define EOFF  4608
#define WOFF  9216

// ---------------- scratch ----------------
__device__ float g_h[NND * HID];
__device__ float g_e[NE * HID];
__device__ float g_eij[NE * HID];
__device__ float g_Ax[NND * HID];
__device__ float g_Bx[NND * HID];
__device__ float g_Dx[NND * HID];
__device__ float g_Ex[NND * HID];
__device__ float g_num[NND * HID];
__device__ float g_den[NND * HID];
__device__ float g_part[2048 * 256];
__device__ float g_scN[HID], g_shN[HID], g_scE[HID], g_shE[HID];
__device__ float g_pool[BATCH * HID];
__device__ float g_t1[BATCH * 64];
__device__ float g_t2[BATCH * 32];
// edge sort
__device__ int g_cnt[NND];
__device__ int g_src2[NE];
__device__ int g_dst2[NE];
__device__ int g_perm[NE];

__device__ __forceinline__ unsigned f2tf(float f) {
    unsigned u; asm("cvt.rna.tf32.f32 %0, %1;" : "=r"(u) : "f"(f)); return u;
}
__device__ __forceinline__ void mma8(float* d, const unsigned* a, const unsigned* b) {
    asm volatile("mma.sync.aligned.m16n8k8.row.col.f32.tf32.tf32.f32 "
        "{%0,%1,%2,%3}, {%4,%5,%6,%7}, {%8,%9}, {%0,%1,%2,%3};"
        : "+f"(d[0]), "+f"(d[1]), "+f"(d[2]), "+f"(d[3])
        : "r"(a[0]), "r"(a[1]), "r"(a[2]), "r"(a[3]), "r"(b[0]), "r"(b[1]));
}
__device__ __forceinline__ void red4(float* p, float4 v) {
    asm volatile("red.global.add.v4.f32 [%0], {%1,%2,%3,%4};"
        :: "l"(p), "f"(v.x), "f"(v.y), "f"(v.z), "f"(v.w) : "memory");
}
__device__ __forceinline__ void cp16(uint32_t dst, const float* src) {
    asm volatile("cp.async.ca.shared.global [%0], [%1], 16;" :: "r"(dst), "l"(src));
}
#define CPCOMMIT asm volatile("cp.async.commit_group;" ::)
#define CPWAIT0  asm volatile("cp.async.wait_group 0;" ::)
#define CPWAIT1  asm volatile("cp.async.wait_group 1;" ::)

// split-on-the-fly fragment helpers
__device__ __forceinline__ void splitv(float f, unsigned& hi, unsigned& lo) {
    hi = f2tf(f);
    lo = f2tf(f - __uint_as_float(hi));
}

// ---------------- edge counting sort ----------------
__global__ void hist_zero_kernel() {
    int i = blockIdx.x * blockDim.x + threadIdx.x;
    if (i < NND) g_cnt[i] = 0;
}
__global__ void hist_kernel(const int* __restrict__ dst) {
    int i = blockIdx.x * blockDim.x + threadIdx.x;
    if (i < NE) atomicAdd(&g_cnt[dst[i]], 1);
}
__global__ __launch_bounds__(1024) void scan_kernel() {
    __shared__ int ssum[1024];
    int tid = threadIdx.x;
    int base = tid * 16;
    int loc[16]; int s = 0;
#pragma unroll
    for (int i = 0; i < 16; i++) { loc[i] = s; s += g_cnt[base + i]; }
    ssum[tid] = s;
    __syncthreads();
    for (int off = 1; off < 1024; off <<= 1) {
        int v = (tid >= off) ? ssum[tid - off] : 0;
        __syncthreads();
        ssum[tid] += v;
        __syncthreads();
    }
    int pre = (tid == 0) ? 0 : ssum[tid - 1];
#pragma unroll
    for (int i = 0; i < 16; i++) g_cnt[base + i] = pre + loc[i];
}
__global__ void scatter_kernel(const int* __restrict__ src, const int* __restrict__ dst) {
    int i = blockIdx.x * blockDim.x + threadIdx.x;
    if (i >= NE) return;
    int d = dst[i];
    int pos = atomicAdd(&g_cnt[d], 1);
    g_perm[pos] = i;
    g_src2[pos] = src[i];
    g_dst2[pos] = d;
}

// ---------------- input projection ----------------
__global__ void input_proj_kernel(const float* __restrict__ x, const float* __restrict__ pe,
                                  const float* __restrict__ nw, const float* __restrict__ nb,
                                  const float* __restrict__ pw, const float* __restrict__ pb) {
    int row = blockIdx.x;
    int c = threadIdx.x;
    __shared__ float xs[64];
    __shared__ float ps[16];
    if (c < 64) xs[c] = x[row * 64 + c];
    else if (c < 80) ps[c - 64] = pe[row * 16 + (c - 64)];
    __syncthreads();
    float acc;
    if (c < 112) {
        acc = nb[c];
#pragma unroll
        for (int k = 0; k < 64; k++) acc += xs[k] * nw[k * 112 + c];
    } else {
        int cc = c - 112;
        acc = pb[cc];
#pragma unroll
        for (int k = 0; k < 16; k++) acc += ps[k] * pw[k * 16 + cc];
    }
    g_h[row * HID + c] = acc;
}

// ================= pipelined 3xTF32 GEMM (plain / node-fold), multi-weight via blockIdx.y ====
__global__ __launch_bounds__(256, 2) void gemm_tc(
    const float* __restrict__ A, const float* __restrict__ foldE, int doFold,
    const float* __restrict__ W0, const float* __restrict__ W1,
    const float* __restrict__ W2, const float* __restrict__ W3,
    const float* __restrict__ b0, const float* __restrict__ b1,
    const float* __restrict__ b2, const float* __restrict__ b3,
    float* __restrict__ C0, float* __restrict__ C1,
    float* __restrict__ C2, float* __restrict__ C3) {
    int y = blockIdx.y;
    const float* W = (y == 0) ? W0 : (y == 1) ? W1 : (y == 2) ? W2 : W3;
    const float* bb = (y == 0) ? b0 : (y == 1) ? b1 : (y == 2) ? b2 : b3;
    float* C = (y == 0) ? C0 : (y == 1) ? C1 : (y == 2) ? C2 : C3;

    extern __shared__ float smf[];
    uint32_t sa = (uint32_t)__cvta_generic_to_shared(smf);
    int tid = threadIdx.x, lane = tid & 31, wid = tid >> 5;
    int wm = wid & 3, wn = wid >> 2, g = lane >> 2, t = lane & 3;
    int r0 = blockIdx.x * 128;
    int arow = tid >> 1, acb = (tid & 1) * 16;
    int wrow = tid >> 3, wcb = (tid & 7) * 16;

    float acc[2][8][4];
#pragma unroll
    for (int i = 0; i < 2; i++)
#pragma unroll
        for (int j = 0; j < 8; j++)
#pragma unroll
            for (int q = 0; q < 4; q++) acc[i][j][q] = 0.f;

    const float* Agp = A + (size_t)(r0 + arow) * HID + acb;
    const float* Egp = foldE ? (foldE + (size_t)(r0 + arow) * HID + acb) : nullptr;
    const float* Wgp = W + (size_t)wrow * HID + wcb;

#define PCOPY(k0, s) do { \
    uint32_t ab = sa + (unsigned)((s)*STAGE + arow*36 + acb) * 4; \
    _Pragma("unroll") for (int q = 0; q < 4; q++) cp16(ab + q*16, Agp + (k0) + q*4); \
    if (doFold) { \
        uint32_t eb = sa + (unsigned)((s)*STAGE + EOFF + arow*36 + acb) * 4; \
        _Pragma("unroll") for (int q = 0; q < 4; q++) cp16(eb + q*16, Egp + (k0) + q*4); \
    } \
    uint32_t wb2 = sa + (unsigned)((s)*STAGE + WOFF + wrow*136 + wcb) * 4; \
    _Pragma("unroll") for (int q = 0; q < 4; q++) cp16(wb2 + q*16, Wgp + (size_t)(k0)*HID + q*4); \
} while (0)

    PCOPY(0, 0); CPCOMMIT;
    for (int k = 0; k < 4; k++) {
        int s = k & 1;
        if (k < 3) { PCOPY((k + 1) * 32, (k + 1) & 1); CPCOMMIT; CPWAIT1; }
        else CPWAIT0;
        __syncthreads();
        if (doFold) {
            float* Asf = smf + s * STAGE;
            float* Esf = Asf + EOFF;
            int k0 = k * 32;
#pragma unroll
            for (int q = 0; q < 4; q++) {
                int kc = acb + q * 4;
                float4 a = *(float4*)&Asf[arow * 36 + kc];
                float4 e = *(float4*)&Esf[arow * 36 + kc];
                float4 sc = *(const float4*)&g_scN[k0 + kc];
                float4 sh = *(const float4*)&g_shN[k0 + kc];
                a.x = fmaxf(a.x * sc.x + sh.x, 0.f) + e.x;
                a.y = fmaxf(a.y * sc.y + sh.y, 0.f) + e.y;
                a.z = fmaxf(a.z * sc.z + sh.z, 0.f) + e.z;
                a.w = fmaxf(a.w * sc.w + sh.w, 0.f) + e.w;
                *(float4*)&Asf[arow * 36 + kc] = a;
            }
            __syncthreads();
        }
        const float* Asf = smf + s * STAGE;
        const float* Wsf = smf + s * STAGE + WOFF;
#pragma unroll
        for (int kk = 0; kk < 32; kk += 8) {
            unsigned ah[2][4], al[2][4];
#pragma unroll
            for (int mt = 0; mt < 2; mt++) {
                int rb = wm * 32 + mt * 16 + g;
                float a0 = Asf[rb * 36 + kk + t];
                float a1 = Asf[(rb + 8) * 36 + kk + t];
                float a2 = Asf[rb * 36 + kk + t + 4];
                float a3 = Asf[(rb + 8) * 36 + kk + t + 4];
                splitv(a0, ah[mt][0], al[mt][0]);
                splitv(a1, ah[mt][1], al[mt][1]);
                splitv(a2, ah[mt][2], al[mt][2]);
                splitv(a3, ah[mt][3], al[mt][3]);
            }
#pragma unroll
            for (int nt = 0; nt < 8; nt++) {
                int cb = wn * 64 + nt * 8 + g;
                float bv0 = Wsf[(kk + t) * 136 + cb];
                float bv1 = Wsf[(kk + t + 4) * 136 + cb];
                unsigned bh[2], bl[2];
                splitv(bv0, bh[0], bl[0]);
                splitv(bv1, bh[1], bl[1]);
#pragma unroll
                for (int mt = 0; mt < 2; mt++) {
                    mma8(acc[mt][nt], ah[mt], bh);
                    mma8(acc[mt][nt], al[mt], bh);
                    mma8(acc[mt][nt], ah[mt], bl);
                }
            }
        }
        __syncthreads();
    }
#undef PCOPY
#pragma unroll
    for (int mt = 0; mt < 2; mt++) {
#pragma unroll
        for (int nt = 0; nt < 8; nt++) {
            int c = wn * 64 + nt * 8 + 2 * t;
            float bx = bb[c], by = bb[c + 1];
            int r = r0 + wm * 32 + mt * 16 + g;
            *(float2*)&C[r * HID + c] = make_float2(acc[mt][nt][0] + bx, acc[mt][nt][1] + by);
            *(float2*)&C[(r + 8) * HID + c] = make_float2(acc[mt][nt][2] + bx, acc[mt][nt][3] + by);
        }
    }
}

// ================= pipelined edge GEMM (sorted): fold transform + segment-reduce epilogue ====
__global__ __launch_bounds__(256, 2) void gemm_tc_edge(
    const float* __restrict__ A, const float* __restrict__ foldE, float* __restrict__ foldOut,
    const float* __restrict__ W, const float* __restrict__ bias,
    float* __restrict__ C,
    const float* __restrict__ Dx, const float* __restrict__ Ex, const float* __restrict__ Bx,
    int doStats, int permA, int permF, int writeC, int writeFold) {
    extern __shared__ float smf[];
    uint32_t sa = (uint32_t)__cvta_generic_to_shared(smf);
    float* tile = smf;                         // overlay after mainloop (128x132)
    int* sidx = (int*)(smf + 2 * STAGE);
    int* didx = sidx + 128;
    int* pidx = didx + 128;

    int tid = threadIdx.x, lane = tid & 31, wid = tid >> 5;
    int wm = wid & 3, wn = wid >> 2, g = lane >> 2, t = lane & 3;
    int r0 = blockIdx.x * 128;
    int arow = tid >> 1, acb = (tid & 1) * 16;
    int wrow = tid >> 3, wcb = (tid & 7) * 16;

    if (tid < 128) {
        sidx[tid] = g_src2[r0 + tid];
        didx[tid] = g_dst2[r0 + tid];
        pidx[tid] = g_perm[r0 + tid];
    }
    __syncthreads();

    float acc[2][8][4];
#pragma unroll
    for (int i = 0; i < 2; i++)
#pragma unroll
        for (int j = 0; j < 8; j++)
#pragma unroll
            for (int q = 0; q < 4; q++) acc[i][j][q] = 0.f;

    int doFold = (foldE != nullptr);
    int aIdx = permA ? pidx[arow] : (r0 + arow);
    int fIdx = permF ? pidx[arow] : (r0 + arow);
    const float* Agp = A + (size_t)aIdx * HID + acb;
    const float* Egp = doFold ? (foldE + (size_t)fIdx * HID + acb) : nullptr;
    const float* Wgp = W + (size_t)wrow * HID + wcb;

#define ECOPY(k0, s) do { \
    uint32_t ab = sa + (unsigned)((s)*STAGE + arow*36 + acb) * 4; \
    _Pragma("unroll") for (int q = 0; q < 4; q++) cp16(ab + q*16, Agp + (k0) + q*4); \
    if (doFold) { \
        uint32_t eb = sa + (unsigned)((s)*STAGE + EOFF + arow*36 + acb) * 4; \
        _Pragma("unroll") for (int q = 0; q < 4; q++) cp16(eb + q*16, Egp + (k0) + q*4); \
    } \
    uint32_t wb2 = sa + (unsigned)((s)*STAGE + WOFF + wrow*136 + wcb) * 4; \
    _Pragma("unroll") for (int q = 0; q < 4; q++) cp16(wb2 + q*16, Wgp + (size_t)(k0)*HID + q*4); \
} while (0)

    ECOPY(0, 0); CPCOMMIT;
    for (int k = 0; k < 4; k++) {
        int s = k & 1;
        if (k < 3) { ECOPY((k + 1) * 32, (k + 1) & 1); CPCOMMIT; CPWAIT1; }
        else CPWAIT0;
        __syncthreads();
        if (doFold) {
            float* Asf = smf + s * STAGE;
            float* Esf = Asf + EOFF;
            int k0 = k * 32;
#pragma unroll
            for (int q = 0; q < 4; q++) {
                int kc = acb + q * 4;
                float4 a = *(float4*)&Asf[arow * 36 + kc];
                float4 e = *(float4*)&Esf[arow * 36 + kc];
                float4 sc = *(const float4*)&g_scE[k0 + kc];
                float4 sh = *(const float4*)&g_shE[k0 + kc];
                a.x = fmaxf(a.x * sc.x + sh.x, 0.f) + e.x;
                a.y = fmaxf(a.y * sc.y + sh.y, 0.f) + e.y;
                a.z = fmaxf(a.z * sc.z + sh.z, 0.f) + e.z;
                a.w = fmaxf(a.w * sc.w + sh.w, 0.f) + e.w;
                *(float4*)&Asf[arow * 36 + kc] = a;
                if (writeFold) *(float4*)&foldOut[(size_t)(r0 + arow) * HID + k0 + kc] = a;
            }
            __syncthreads();
        }
        const float* Asf = smf + s * STAGE;
        const float* Wsf = smf + s * STAGE + WOFF;
#pragma unroll
        for (int kk = 0; kk < 32; kk += 8) {
            unsigned ah[2][4], al[2][4];
#pragma unroll
            for (int mt = 0; mt < 2; mt++) {
                int rb = wm * 32 + mt * 16 + g;
                float a0 = Asf[rb * 36 + kk + t];
                float a1 = Asf[(rb + 8) * 36 + kk + t];
                float a2 = Asf[rb * 36 + kk + t + 4];
                float a3 = Asf[(rb + 8) * 36 + kk + t + 4];
                splitv(a0, ah[mt][0], al[mt][0]);
                splitv(a1, ah[mt][1], al[mt][1]);
                splitv(a2, ah[mt][2], al[mt][2]);
                splitv(a3, ah[mt][3], al[mt][3]);
            }
#pragma unroll
            for (int nt = 0; nt < 8; nt++) {
                int cb = wn * 64 + nt * 8 + g;
                float bv0 = Wsf[(kk + t) * 136 + cb];
                float bv1 = Wsf[(kk + t + 4) * 136 + cb];
                unsigned bh[2], bl[2];
                splitv(bv0, bh[0], bl[0]);
                splitv(bv1, bh[1], bl[1]);
#pragma unroll
                for (int mt = 0; mt < 2; mt++) {
                    mma8(acc[mt][nt], ah[mt], bh);
                    mma8(acc[mt][nt], al[mt], bh);
                    mma8(acc[mt][nt], ah[mt], bl);
                }
            }
        }
        __syncthreads();
    }
#undef ECOPY
    // stage accumulators to smem tile (overlays stage buffers)
#pragma unroll
    for (int mt = 0; mt < 2; mt++) {
#pragma unroll
        for (int nt = 0; nt < 8; nt++) {
            int c = wn * 64 + nt * 8 + 2 * t;
            int r = wm * 32 + mt * 16 + g;
            tile[r * 132 + c] = acc[mt][nt][0];
            tile[r * 132 + c + 1] = acc[mt][nt][1];
            tile[(r + 8) * 132 + c] = acc[mt][nt][2];
            tile[(r + 8) * 132 + c + 1] = acc[mt][nt][3];
        }
    }
    __syncthreads();
    // epilogue: warp = 16 contiguous sorted rows, lane = 4 channels; segment-reduce on dst runs
    {
        int c4 = (tid & 31) * 4;
        int chunk = tid >> 5;  // 0..7
        float4 bcv = *(const float4*)&bias[c4];
        float4 s1v = make_float4(0.f, 0.f, 0.f, 0.f);
        float4 s2v = make_float4(0.f, 0.f, 0.f, 0.f);
        float4 accN = make_float4(0.f, 0.f, 0.f, 0.f);
        float4 accD = make_float4(0.f, 0.f, 0.f, 0.f);
        int curd = didx[chunk * 16];
#pragma unroll 4
        for (int rr = 0; rr < 16; rr++) {
            int r = chunk * 16 + rr;
            int d = didx[r], s = sidx[r];
            if (d != curd) {
                red4(&g_num[curd * HID + c4], accN);
                red4(&g_den[curd * HID + c4], accD);
                accN = make_float4(0.f, 0.f, 0.f, 0.f);
                accD = make_float4(0.f, 0.f, 0.f, 0.f);
                curd = d;
            }
            float4 tv = *(float4*)&tile[r * 132 + c4];
            float4 dx = *(const float4*)&Dx[d * HID + c4];
            float4 ex = *(const float4*)&Ex[s * HID + c4];
            float4 bx = *(const float4*)&Bx[s * HID + c4];
            float4 v;
            v.x = tv.x + bcv.x + dx.x + ex.x;
            v.y = tv.y + bcv.y + dx.y + ex.y;
            v.z = tv.z + bcv.z + dx.z + ex.z;
            v.w = tv.w + bcv.w + dx.w + ex.w;
            if (writeC) *(float4*)&C[(size_t)(r0 + r) * HID + c4] = v;
            float4 sg;
            sg.x = 1.f / (1.f + __expf(-v.x));
            sg.y = 1.f / (1.f + __expf(-v.y));
            sg.z = 1.f / (1.f + __expf(-v.z));
            sg.w = 1.f / (1.f + __expf(-v.w));
            accN.x += sg.x * bx.x; accN.y += sg.y * bx.y;
            accN.z += sg.z * bx.z; accN.w += sg.w * bx.w;
            accD.x += sg.x; accD.y += sg.y; accD.z += sg.z; accD.w += sg.w;
            s1v.x += v.x; s1v.y += v.y; s1v.z += v.z; s1v.w += v.w;
            s2v.x += v.x * v.x; s2v.y += v.y * v.y; s2v.z += v.z * v.z; s2v.w += v.w * v.w;
        }
        red4(&g_num[curd * HID + c4], accN);
        red4(&g_den[curd * HID + c4], accD);
        if (doStats) {
            red4(&g_part[blockIdx.x * 256 + c4], s1v);
            red4(&g_part[blockIdx.x * 256 + 128 + c4], s2v);
        }
    }
}

// ---------------- zero num/den/part ----------------
__global__ void zero_nd_kernel() {
    int i = blockIdx.x * blockDim.x + threadIdx.x;
    float4 z = make_float4(0.f, 0.f, 0.f, 0.f);
    ((float4*)g_num)[i] = z;
    ((float4*)g_den)[i] = z;
    if (i < 2048 * 256 / 4) ((float4*)g_part)[i] = z;
}

// ---------------- h_new = Ax + num/(den+eps) fused with BN partials ----------------
__global__ void node_hnew_stats_kernel() {
    int c = threadIdx.x;
    float s = 0.f, ss = 0.f;
    for (int r = blockIdx.x; r < NND; r += gridDim.x) {
        int i = r * HID + c;
        float v = g_Ax[i] + g_num[i] / (g_den[i] + 1e-6f);
        g_Ax[i] = v;
        s += v; ss += v * v;
    }
    g_part[blockIdx.x * 256 + c] = s;
    g_part[blockIdx.x * 256 + 128 + c] = ss;
}

// ---------------- BN finalize ----------------
__global__ void bn_finalize2(int G, float invM, const float* __restrict__ gamma,
                             const float* __restrict__ beta,
                             float* __restrict__ scale, float* __restrict__ shift) {
    int c = blockIdx.x;
    int tid = threadIdx.x;
    double s = 0.0, ss = 0.0;
    for (int gi = tid; gi < G; gi += 256) {
        s  += (double)g_part[gi * 256 + c];
        ss += (double)g_part[gi * 256 + 128 + c];
    }
    __shared__ double rs[256], rss[256];
    rs[tid] = s; rss[tid] = ss;
    __syncthreads();
    for (int o = 128; o > 0; o >>= 1) {
        if (tid < o) { rs[tid] += rs[tid + o]; rss[tid] += rss[tid + o]; }
        __syncthreads();
    }
    if (tid == 0) {
        double mu = rs[0] * (double)invM;
        double var = rss[0] * (double)invM - mu * mu;
        float inv = rsqrtf((float)var + 1e-5f);
        float scv = gamma[c] * inv;
        scale[c] = scv;
        shift[c] = beta[c] - (float)mu * scv;
    }
}

// ---------------- dense attention per (head, batch graph) ----------------
__global__ void attn_kernel(const float* __restrict__ q, const float* __restrict__ k,
                            const float* __restrict__ v, const float* __restrict__ sph,
                            float* __restrict__ o) {
    extern __shared__ float smf[];
    float* ks = smf;
    float* vs = smf + 128 * 36;
    float* ps = smf + 2 * 128 * 36;
    int head = blockIdx.x, b = blockIdx.y;
    int s = threadIdx.x;
    int nodebase = (b * SEQ + s) * HID + head * 32;
    float qr[32];
#pragma unroll
    for (int d4 = 0; d4 < 8; d4++) {
        float4 tq = *(const float4*)&q[nodebase + d4 * 4];
        qr[d4 * 4] = tq.x; qr[d4 * 4 + 1] = tq.y; qr[d4 * 4 + 2] = tq.z; qr[d4 * 4 + 3] = tq.w;
        *(float4*)&ks[s * 36 + d4 * 4] = *(const float4*)&k[nodebase + d4 * 4];
        *(float4*)&vs[s * 36 + d4 * 4] = *(const float4*)&v[nodebase + d4 * 4];
    }
    __syncthreads();
    const float isd = 0.17677669529663687f;
    for (int t = 0; t < SEQ; t++) {
        float acc = 0.f;
#pragma unroll
        for (int d4 = 0; d4 < 8; d4++) {
            float4 kk = *(float4*)&ks[t * 36 + d4 * 4];
            acc += qr[d4 * 4] * kk.x + qr[d4 * 4 + 1] * kk.y +
                   qr[d4 * 4 + 2] * kk.z + qr[d4 * 4 + 3] * kk.w;
        }
        ps[s * 133 + t] = acc * isd;
    }
    __syncthreads();
    const float* sb = sph + b * SEQ * SEQ;
    for (int i = s; i < SEQ * SEQ; i += 128) {
        int s2 = i >> 7, t2 = i & 127;
        ps[s2 * 133 + t2] *= sb[i];
    }
    __syncthreads();
    float mx = -1e30f;
    for (int t = 0; t < SEQ; t++) mx = fmaxf(mx, ps[s * 133 + t]);
    float sum = 0.f;
    for (int t = 0; t < SEQ; t++) {
        float e = __expf(ps[s * 133 + t] - mx);
        ps[s * 133 + t] = e;
        sum += e;
    }
    float inv = 1.f / sum;
    float acc[32];
#pragma unroll
    for (int d = 0; d < 32; d++) acc[d] = 0.f;
    for (int t = 0; t < SEQ; t++) {
        float p = ps[s * 133 + t] * inv;
#pragma unroll
        for (int d4 = 0; d4 < 8; d4++) {
            float4 vvv = *(float4*)&vs[t * 36 + d4 * 4];
            acc[d4 * 4] += p * vvv.x; acc[d4 * 4 + 1] += p * vvv.y;
            acc[d4 * 4 + 2] += p * vvv.z; acc[d4 * 4 + 3] += p * vvv.w;
        }
    }
#pragma unroll
    for (int d4 = 0; d4 < 8; d4++) {
        float4 t4 = make_float4(acc[d4 * 4], acc[d4 * 4 + 1], acc[d4 * 4 + 2], acc[d4 * 4 + 3]);
        *(float4*)&o[nodebase + d4 * 4] = t4;
    }
}

// ---------------- mean pool + tiny MLP ----------------
__global__ void pool_kernel() {
    int b = blockIdx.x, c = threadIdx.x;
    float s = 0.f;
    for (int i = 0; i < SEQ; i++) s += g_h[(b * SEQ + i) * HID + c];
    g_pool[b * HID + c] = s * (1.f / 128.f);
}
__global__ void mlp_kernel(const float* __restrict__ in, const float* __restrict__ W,
                           const float* __restrict__ bias, float* __restrict__ out,
                           int K, int Ncol, int doRelu) {
    int r = blockIdx.x;
    __shared__ float xs[128];
    if ((int)threadIdx.x < K) xs[threadIdx.x] = in[r * K + threadIdx.x];
    __syncthreads();
    int c = threadIdx.x;
    if (c < Ncol) {
        float acc = bias[c];
        for (int k = 0; k < K; k++) acc += xs[k] * W[k * Ncol + c];
        if (doRelu) acc = fmaxf(acc, 0.f);
        out[r * Ncol + c] = acc;
    }
}

// ---------------- launch ----------------
extern "C" void kernel_launch(void* const* d_in, const int* in_sizes, int n_in,
                              void* d_out, int out_size) {
    const float* x        = (const float*)d_in[0];
    const float* pe       = (const float*)d_in[1];
    const float* edge_attr= (const float*)d_in[2];
    const float* sph      = (const float*)d_in[3];
    const float* node_w   = (const float*)d_in[4];
    const float* node_b   = (const float*)d_in[5];
    const float* pe_w     = (const float*)d_in[6];
    const float* pe_b     = (const float*)d_in[7];
    const float* Aw       = (const float*)d_in[8];
    const float* Ab       = (const float*)d_in[9];
    const float* Bw       = (const float*)d_in[10];
    const float* Bb       = (const float*)d_in[11];
    const float* Cw       = (const float*)d_in[12];
    const float* Cb       = (const float*)d_in[13];
    const float* Dw       = (const float*)d_in[14];
    const float* Db       = (const float*)d_in[15];
    const float* Ew       = (const float*)d_in[16];
    const float* Eb       = (const float*)d_in[17];
    const float* bnxg     = (const float*)d_in[18];
    const float* bnxb     = (const float*)d_in[19];
    const float* bneg     = (const float*)d_in[20];
    const float* bneb     = (const float*)d_in[21];
    const float* attw     = (const float*)d_in[22];
    const float* attb     = (const float*)d_in[23];
    const float* m1w      = (const float*)d_in[24];
    const float* m1b      = (const float*)d_in[25];
    const float* m2w      = (const float*)d_in[26];
    const float* m2b      = (const float*)d_in[27];
    const float* m3w      = (const float*)d_in[28];
    const float* m3b      = (const float*)d_in[29];
    const int*   ei       = (const int*)d_in[30];
    float* out = (float*)d_out;

    float *p_h, *p_e, *p_eij, *p_Ax, *p_Bx, *p_Dx, *p_Ex, *p_num, *p_den;
    float *p_scN, *p_shN, *p_scE, *p_shE, *p_pool, *p_t1, *p_t2;
    cudaGetSymbolAddress((void**)&p_h,   g_h);
    cudaGetSymbolAddress((void**)&p_e,   g_e);
    cudaGetSymbolAddress((void**)&p_eij, g_eij);
    cudaGetSymbolAddress((void**)&p_Ax,  g_Ax);
    cudaGetSymbolAddress((void**)&p_Bx,  g_Bx);
    cudaGetSymbolAddress((void**)&p_Dx,  g_Dx);
    cudaGetSymbolAddress((void**)&p_Ex,  g_Ex);
    cudaGetSymbolAddress((void**)&p_num, g_num);
    cudaGetSymbolAddress((void**)&p_den, g_den);
    cudaGetSymbolAddress((void**)&p_scN, g_scN);
    cudaGetSymbolAddress((void**)&p_shN, g_shN);
    cudaGetSymbolAddress((void**)&p_scE, g_scE);
    cudaGetSymbolAddress((void**)&p_shE, g_shE);
    cudaGetSymbolAddress((void**)&p_pool,g_pool);
    cudaGetSymbolAddress((void**)&p_t1,  g_t1);
    cudaGetSymbolAddress((void**)&p_t2,  g_t2);

    const int* src = ei;
    const int* dst = ei + NE;
    const int ATTN_SMEM = (2 * 128 * 36 + 128 * 133) * 4;
    const int PLAIN_SMEM = 2 * STAGE * 4;                 // 108544
    const int EDGE_SMEM = (2 * STAGE + 384) * 4;          // 110080
    cudaFuncSetAttribute(attn_kernel, cudaFuncAttributeMaxDynamicSharedMemorySize, ATTN_SMEM);
    cudaFuncSetAttribute(gemm_tc, cudaFuncAttributeMaxDynamicSharedMemorySize, PLAIN_SMEM);
    cudaFuncSetAttribute(gemm_tc_edge, cudaFuncAttributeMaxDynamicSharedMemorySize, EDGE_SMEM);

    // edge counting sort by dst (once per call)
    hist_zero_kernel<<<NND / 256, 256>>>();
    hist_kernel<<<NE / 256, 256>>>(dst);
    scan_kernel<<<1, 1024>>>();
    scatter_kernel<<<NE / 256, 256>>>(src, dst);

    input_proj_kernel<<<NND, 128>>>(x, pe, node_w, node_b, pe_w, pe_b);

    for (int l = 0; l < NL; l++) {
        zero_nd_kernel<<<NND * HID / 4 / 256, 256>>>();
        // A,B,D,E projections (no fold)
        dim3 g4(NND / 128, 4);
        gemm_tc<<<g4, 256, PLAIN_SMEM>>>(p_h, nullptr, 0,
            Aw + l * WSZ, Bw + l * WSZ, Dw + l * WSZ, Ew + l * WSZ,
            Ab + l * HID, Bb + l * HID, Db + l * HID, Eb + l * HID,
            p_Ax, p_Bx, p_Dx, p_Ex);
        // edge GEMM with fold + segment-reduce epilogue
        const float* eA    = (l == 0) ? edge_attr : p_eij;
        const float* foldE = (l == 0) ? nullptr : ((l == 1) ? edge_attr : p_e);
        int permA = (l == 0) ? 1 : 0;
        int permF = (l == 1) ? 1 : 0;
        int last = (l == NL - 1);
        gemm_tc_edge<<<NE / 128, 256, EDGE_SMEM>>>(
            eA, foldE, p_e, Cw + l * WSZ, Cb + l * HID, p_eij,
            p_Dx, p_Ex, p_Bx, last ? 0 : 1, permA, permF,
            last ? 0 : 1, last ? 0 : 1);
        if (!last)
            bn_finalize2<<<HID, 256>>>(2048, 1.f / NE, bneg + l * HID, bneb + l * HID, p_scE, p_shE);
        node_hnew_stats_kernel<<<1024, 128>>>();
        bn_finalize2<<<HID, 256>>>(1024, 1.f / NND, bnxg + l * HID, bnxb + l * HID, p_scN, p_shN);
        // q,k,v projections with fused node BN fold (h' never materialized)
        dim3 g3(NND / 128, 3);
        gemm_tc<<<g3, 256, PLAIN_SMEM>>>(p_Ax, p_h, 1,
            attw + 0 * WSZ, attw + 1 * WSZ, attw + 2 * WSZ, attw + 2 * WSZ,
            attb + 0 * HID, attb + 1 * HID, attb + 2 * HID, attb + 2 * HID,
            p_den, p_Bx, p_Dx, p_Dx);
        dim3 ag(4, BATCH);
        attn_kernel<<<ag, 128, ATTN_SMEM>>>(p_den, p_Bx, p_Dx, sph, p_Ex);
        dim3 g1(NND / 128, 1);
        gemm_tc<<<g1, 256, PLAIN_SMEM>>>(p_Ex, nullptr, 0,
            attw + 3 * WSZ, attw + 3 * WSZ, attw + 3 * WSZ, attw + 3 * WSZ,
            attb + 3 * HID, attb + 3 * HID, attb + 3 * HID, attb + 3 * HID,
            p_h, p_h, p_h, p_h);
    }
    pool_kernel<<<BATCH, 128>>>();
    mlp_kernel<<<BATCH, 128>>>(p_pool, m1w, m1b, p_t1, 128, 64, 1);
    mlp_kernel<<<BATCH, 128>>>(p_t1, m2w, m2b, p_t2, 64, 32, 1);
    mlp_kernel<<<BATCH, 128>>>(p_t2, m3w, m3b, out, 32, 10, 0);
}